// round 1
// baseline (speedup 1.0000x reference)
#include <cuda_runtime.h>
#include <math.h>

#define TOK 32768      // B*N = 4*8192
#define DIM 256
#define HIDW 512
#define H2 1024
#define QKD 64
#define GRP 256
#define NG 32          // groups per sequence
#define NBATCH 4
#define NLAYER 8

// ---------------- scratch (device globals; no allocation allowed) ----------
__device__ float g_h[TOK*DIM];
__device__ float g_nx[TOK*DIM];
__device__ float g_hid[TOK*H2];
__device__ float g_qk[TOK*QKD];
__device__ float g_quad[TOK*HIDW];
__device__ float g_kv[NBATCH*NG*QKD*HIDW];
__device__ float g_bias[GRP*GRP];
__device__ float g_part[NBATCH*NG*DIM];

__device__ __forceinline__ float siluf(float x){ return x/(1.0f+expf(-x)); }

// ---------------- embed: h = x@W_emb + b_emb + pos ------------------------
__global__ void embed_kernel(const float* __restrict__ x, const float* __restrict__ W,
                             const float* __restrict__ be, const float* __restrict__ pos){
  int row = blockIdx.x;
  int n = row & 8191;
  int d = threadIdx.x;
  __shared__ float xs[8];
  if (d < 5) xs[d] = x[row*5+d];
  __syncthreads();
  float acc = be[d] + pos[n*DIM+d];
  #pragma unroll
  for (int k=0;k<5;k++) acc = fmaf(xs[k], W[k*DIM+d], acc);
  g_h[row*DIM+d] = acc;
}

// ---------------- layernorm ------------------------------------------------
__global__ void ln_kernel(const float* __restrict__ gl, const float* __restrict__ bl){
  int row = blockIdx.x, d = threadIdx.x;
  float v = g_h[row*DIM+d];
  __shared__ float red[8];
  float s = v;
  #pragma unroll
  for (int o=16;o>0;o>>=1) s += __shfl_xor_sync(0xffffffffu, s, o);
  if ((d&31)==0) red[d>>5] = s;
  __syncthreads();
  float tot = 0.f;
  #pragma unroll
  for (int i=0;i<8;i++) tot += red[i];
  float mu = tot * (1.0f/DIM);
  float dv = v - mu;
  __syncthreads();
  float sq = dv*dv;
  #pragma unroll
  for (int o=16;o>0;o>>=1) sq += __shfl_xor_sync(0xffffffffu, sq, o);
  if ((d&31)==0) red[d>>5] = sq;
  __syncthreads();
  float vt = 0.f;
  #pragma unroll
  for (int i=0;i<8;i++) vt += red[i];
  float var = vt*(1.0f/DIM);
  g_nx[row*DIM+d] = fmaf(dv*rsqrtf(var+1e-5f), gl[d], bl[d]);
}

// ---------------- SGEMM, compile-time operand selection --------------------
// MODE 0: g_hid = silu(g_nx @ Wh + bh)   [32768,256]x[256,1024]
// MODE 1: g_qk  = silu(g_nx @ Wqk + bqk) [32768,256]x[256,64]
// MODE 2: g_h  += g_quad @ Wo + bo       [32768,512]x[512,256]
template<int MODE>
__global__ void __launch_bounds__(256) sgemm_kernel(const float* __restrict__ Bm,
                                                    const float* __restrict__ bias){
  constexpr int N = (MODE==0)?H2:(MODE==1)?QKD:DIM;
  constexpr int K = (MODE==2)?HIDW:DIM;
  const float* A = (MODE==2) ? g_quad : g_nx;
  float* C = (MODE==0) ? g_hid : (MODE==1) ? g_qk : g_h;

  __shared__ float As[16][128];
  __shared__ float Bs[16][64];
  int tid = threadIdx.x;
  int m0 = blockIdx.y*128, n0 = blockIdx.x*64;
  int ty = tid>>4, tx = tid&15;
  float acc[8][4];
  #pragma unroll
  for (int r=0;r<8;r++){ acc[r][0]=0.f; acc[r][1]=0.f; acc[r][2]=0.f; acc[r][3]=0.f; }

  for (int k0=0;k0<K;k0+=16){
    #pragma unroll
    for (int i=0;i<2;i++){
      int idx = tid + i*256;
      int r = idx>>2, c4 = (idx&3)*4;
      float4 v = *(const float4*)(A + (size_t)(m0+r)*K + k0 + c4);
      As[c4+0][r]=v.x; As[c4+1][r]=v.y; As[c4+2][r]=v.z; As[c4+3][r]=v.w;
    }
    {
      int r = tid>>4, c4 = (tid&15)*4;
      *(float4*)&Bs[r][c4] = *(const float4*)(Bm + (size_t)(k0+r)*N + n0 + c4);
    }
    __syncthreads();
    #pragma unroll
    for (int k=0;k<16;k++){
      float a[8];
      #pragma unroll
      for (int r=0;r<8;r++) a[r]=As[k][ty*8+r];
      float4 bv = *(float4*)&Bs[k][tx*4];
      #pragma unroll
      for (int r=0;r<8;r++){
        acc[r][0]=fmaf(a[r],bv.x,acc[r][0]);
        acc[r][1]=fmaf(a[r],bv.y,acc[r][1]);
        acc[r][2]=fmaf(a[r],bv.z,acc[r][2]);
        acc[r][3]=fmaf(a[r],bv.w,acc[r][3]);
      }
    }
    __syncthreads();
  }
  #pragma unroll
  for (int r=0;r<8;r++){
    int row = m0 + ty*8 + r;
    float* Crow = C + (size_t)row*N + n0 + tx*4;
    const float* brow = bias + n0 + tx*4;
    #pragma unroll
    for (int c=0;c<4;c++){
      float v = acc[r][c] + brow[c];
      if (MODE==2) Crow[c] += v;
      else         Crow[c] = siluf(v);
    }
  }
}

// ---------------- T5 rel-pos bias table ------------------------------------
__global__ void bias_kernel(const float* __restrict__ relb){
  int i = blockIdx.x, j = threadIdx.x;
  int n = i - j; if (n < 0) n = 0;
  int bucket;
  if (n < 16) bucket = n;
  else {
    float t = logf((float)n * (1.0f/16.0f)) * (16.0f / 2.0794415416798357f); // /log(8)
    int val = 16 + (int)t;
    bucket = val < 31 ? val : 31;
  }
  g_bias[i*GRP + j] = relb[bucket]*8.0f;   // * sqrt(QKD)
}

// ---------------- fused quad attention + K^T V -----------------------------
#define SQS 68
#define SAS 260
#define ATTN_SMEM ((256*SQS + 64*SQS + 64*SAS + 64*128 + 6*64)*4)

__global__ void __launch_bounds__(256) attn_kernel(const float* __restrict__ gamma,
                                                   const float* __restrict__ beta){
  extern __shared__ float sm[];
  float* sQK  = sm;                 // [256][68]  raw silu(qk)
  float* sQQ  = sQK + 256*SQS;      // [64][68]   quad queries (this i-tile)
  float* sAtt = sQQ + 64*SQS;       // [64][260]  laplace attn tile
  float* sV   = sAtt + 64*SAS;      // [64][128]  v chunk
  float* sG   = sV + 64*128;        // g0,b0,g2,b2,g3,b3 (6*64)
  int it = blockIdx.x, g = blockIdx.y, b = blockIdx.z;
  int tid = threadIdx.x;
  size_t base = (size_t)(b*NG + g)*GRP;

  #pragma unroll
  for (int i=0;i<16;i++){
    int idx = i*256+tid;
    int r = idx>>4, c4 = (idx&15)*4;
    *(float4*)&sQK[r*SQS + c4] = *(const float4*)(g_qk + (base+r)*QKD + c4);
  }
  if (tid < 64){
    sG[tid]     = gamma[tid];      sG[64+tid]  = beta[tid];        // head 0 (qq)
    sG[128+tid] = gamma[128+tid];  sG[192+tid] = beta[128+tid];    // head 2 (qk)
    sG[256+tid] = gamma[192+tid];  sG[320+tid] = beta[192+tid];    // head 3 (lk)
  }
  __syncthreads();
  #pragma unroll
  for (int i=0;i<16;i++){
    int idx = i*256+tid; int ii = idx>>6, d = idx&63;
    sQQ[ii*SQS+d] = fmaf(sQK[(it*64+ii)*SQS + d], sG[d], sG[64+d]);
  }
  __syncthreads();

  int ty = tid>>5, tx = tid&31;
  // phase A: sim = qq.qkk/256 + bias -> laplace -> causal mask
  {
    float acc[8][8];
    #pragma unroll
    for (int r=0;r<8;r++)
      #pragma unroll
      for (int c=0;c<8;c++) acc[r][c]=0.f;
    #pragma unroll 4
    for (int d=0; d<64; d++){
      float g2 = sG[128+d], b2 = sG[192+d];
      float a[8], kk[8];
      #pragma unroll
      for (int r=0;r<8;r++) a[r] = sQQ[(ty*8+r)*SQS + d];
      #pragma unroll
      for (int c=0;c<8;c++) kk[c] = fmaf(sQK[(tx + 32*c)*SQS + d], g2, b2);
      #pragma unroll
      for (int r=0;r<8;r++)
        #pragma unroll
        for (int c=0;c<8;c++) acc[r][c] = fmaf(a[r], kk[c], acc[r][c]);
    }
    #pragma unroll
    for (int r=0;r<8;r++){
      int ig = it*64 + ty*8 + r;
      #pragma unroll
      for (int c=0;c<8;c++){
        int j = tx + 32*c;
        float s = acc[r][c]*(1.0f/256.0f) + g_bias[ig*GRP + j];
        float at = (j <= ig) ? 0.5f*(1.0f + erff((s - 0.70710678f)*0.79788456f)) : 0.0f;
        sAtt[(ty*8+r)*SAS + j] = at;
      }
    }
  }

  float g3r[8], b3r[8];
  #pragma unroll
  for (int r=0;r<8;r++){ g3r[r]=sG[256+ty*8+r]; b3r[r]=sG[320+ty*8+r]; }

  // phase B: quad = attn @ v, plus (it==0) kv = lk^T v / 256
  for (int et=0; et<4; et++){
    float qacc[8][4], kvacc[8][4];
    #pragma unroll
    for (int r=0;r<8;r++)
      #pragma unroll
      for (int c=0;c<4;c++){ qacc[r][c]=0.f; kvacc[r][c]=0.f; }
    for (int jc=0;jc<4;jc++){
      __syncthreads();
      #pragma unroll
      for (int i=0;i<8;i++){
        int idx = i*256+tid;
        int r = idx>>5, c4 = (idx&31)*4;
        *(float4*)&sV[r*128+c4] = *(const float4*)(g_hid + (base + jc*64 + r)*H2 + et*128 + c4);
      }
      __syncthreads();
      #pragma unroll 2
      for (int jj=0;jj<64;jj++){
        int j = jc*64 + jj;
        float4 v4 = *(float4*)&sV[jj*128 + tx*4];
        float a[8];
        #pragma unroll
        for (int r=0;r<8;r++) a[r] = sAtt[(ty*8+r)*SAS + j];
        #pragma unroll
        for (int r=0;r<8;r++){
          qacc[r][0]=fmaf(a[r],v4.x,qacc[r][0]);
          qacc[r][1]=fmaf(a[r],v4.y,qacc[r][1]);
          qacc[r][2]=fmaf(a[r],v4.z,qacc[r][2]);
          qacc[r][3]=fmaf(a[r],v4.w,qacc[r][3]);
        }
        if (it==0){
          #pragma unroll
          for (int r=0;r<8;r++){
            float lk = fmaf(sQK[j*SQS + ty*8 + r], g3r[r], b3r[r]);
            kvacc[r][0]=fmaf(lk,v4.x,kvacc[r][0]);
            kvacc[r][1]=fmaf(lk,v4.y,kvacc[r][1]);
            kvacc[r][2]=fmaf(lk,v4.z,kvacc[r][2]);
            kvacc[r][3]=fmaf(lk,v4.w,kvacc[r][3]);
          }
        }
      }
    }
    #pragma unroll
    for (int r=0;r<8;r++){
      size_t row = base + it*64 + ty*8 + r;
      float4 o; o.x=qacc[r][0]; o.y=qacc[r][1]; o.z=qacc[r][2]; o.w=qacc[r][3];
      *(float4*)(g_quad + row*HIDW + et*128 + tx*4) = o;
    }
    if (it==0){
      #pragma unroll
      for (int r=0;r<8;r++){
        float4 o;
        o.x=kvacc[r][0]*(1.0f/256.0f); o.y=kvacc[r][1]*(1.0f/256.0f);
        o.z=kvacc[r][2]*(1.0f/256.0f); o.w=kvacc[r][3]*(1.0f/256.0f);
        *(float4*)(g_kv + ((size_t)(b*NG+g)*QKD + ty*8 + r)*HIDW + et*128 + tx*4) = o;
      }
    }
  }
}

// ---------------- exclusive cumsum of kv over groups (in place) ------------
__global__ void cumsum_kernel(){
  int b = blockIdx.y;
  int idx = blockIdx.x*256 + threadIdx.x;   // 0..32767 = d*512+e
  float acc = 0.f;
  #pragma unroll
  for (int g=0; g<NG; g++){
    size_t p = ((size_t)(b*NG+g))*(QKD*HIDW) + idx;
    float cur = g_kv[p];
    g_kv[p] = acc;
    acc += cur;
  }
}

// ---------------- linear attention + gated combine -------------------------
#define LIN_SMEM ((64*64 + 64*128 + 128)*4)
__global__ void __launch_bounds__(256) lin_kernel(const float* __restrict__ gamma,
                                                  const float* __restrict__ beta){
  extern __shared__ float sm[];
  float* sLQ  = sm;              // [64][64]
  float* sLKV = sLQ + 64*64;     // [64][128]
  float* sG1  = sLKV + 64*128;   // [64]
  float* sB1  = sG1 + 64;        // [64]
  int et = blockIdx.x & 3, it = blockIdx.x >> 2;
  int g = blockIdx.y, b = blockIdx.z;
  int tid = threadIdx.x, ty = tid>>5, tx = tid&31;
  size_t base = (size_t)(b*NG+g)*GRP;

  if (tid < 64){ sG1[tid]=gamma[64+tid]; sB1[tid]=beta[64+tid]; }   // head 1 (lq)
  #pragma unroll
  for (int i=0;i<4;i++){
    int idx = i*256+tid; int r = idx>>4, c4 = (idx&15)*4;
    *(float4*)&sLQ[r*64+c4] = *(const float4*)(g_qk + (base + it*64 + r)*QKD + c4);
  }
  #pragma unroll
  for (int i=0;i<8;i++){
    int idx=i*256+tid; int r=idx>>5, c4=(idx&31)*4;
    *(float4*)&sLKV[r*128+c4] = *(const float4*)(g_kv + ((size_t)(b*NG+g)*QKD + r)*HIDW + et*128 + c4);
  }
  __syncthreads();
  #pragma unroll
  for (int i=0;i<16;i++){
    int idx=i*256+tid; int r=idx>>6, d=idx&63;
    sLQ[r*64+d] = fmaf(sLQ[r*64+d], sG1[d], sB1[d]);
  }
  __syncthreads();

  float acc[8][4];
  #pragma unroll
  for (int r=0;r<8;r++){ acc[r][0]=0.f; acc[r][1]=0.f; acc[r][2]=0.f; acc[r][3]=0.f; }
  #pragma unroll 4
  for (int d=0; d<64; d++){
    float4 kv4 = *(float4*)&sLKV[d*128 + tx*4];
    float a[8];
    #pragma unroll
    for (int r=0;r<8;r++) a[r] = sLQ[(ty*8+r)*64 + d];
    #pragma unroll
    for (int r=0;r<8;r++){
      acc[r][0]=fmaf(a[r],kv4.x,acc[r][0]);
      acc[r][1]=fmaf(a[r],kv4.y,acc[r][1]);
      acc[r][2]=fmaf(a[r],kv4.z,acc[r][2]);
      acc[r][3]=fmaf(a[r],kv4.w,acc[r][3]);
    }
  }
  #pragma unroll
  for (int r=0;r<8;r++){
    size_t row = base + it*64 + ty*8 + r;
    int e = et*128 + tx*4;
    float4 q  = *(float4*)(g_quad + row*HIDW + e);
    float4 gt = *(float4*)(g_hid + row*H2 + HIDW + e);
    float4 o;
    o.x = gt.x*(q.x+acc[r][0]);
    o.y = gt.y*(q.y+acc[r][1]);
    o.z = gt.z*(q.z+acc[r][2]);
    o.w = gt.w*(q.w+acc[r][3]);
    *(float4*)(g_quad + row*HIDW + e) = o;
  }
}

// ---------------- final mean pool + classifier -----------------------------
__global__ void mean1_kernel(){
  int c = blockIdx.x, b = blockIdx.y, d = threadIdx.x;
  float s = 0.f;
  size_t rb = (size_t)b*8192 + (size_t)c*256;
  for (int r=0;r<256;r++) s += g_h[(rb+r)*DIM + d];
  g_part[(b*NG+c)*DIM + d] = s;
}

__global__ void head_kernel(const float* __restrict__ Wd, const float* __restrict__ bd,
                            float* __restrict__ out){
  int b = blockIdx.x, d = threadIdx.x;
  float s = 0.f;
  for (int c=0;c<NG;c++) s += g_part[(b*NG+c)*DIM + d];
  s *= (1.0f/8192.0f);
  __shared__ float r0[256], r1[256];
  r0[d] = s*Wd[d*2+0];
  r1[d] = s*Wd[d*2+1];
  __syncthreads();
  for (int o=128;o>0;o>>=1){
    if (d<o){ r0[d]+=r0[d+o]; r1[d]+=r1[d+o]; }
    __syncthreads();
  }
  if (d==0){ out[b*2+0]=r0[0]+bd[0]; out[b*2+1]=r1[0]+bd[1]; }
}

// ---------------- host ------------------------------------------------------
extern "C" void kernel_launch(void* const* d_in, const int* in_sizes, int n_in,
                              void* d_out, int out_size){
  const float* x      = (const float*)d_in[0];
  const float* W_emb  = (const float*)d_in[1];
  const float* b_emb  = (const float*)d_in[2];
  const float* pos    = (const float*)d_in[3];
  const float* ln_g   = (const float*)d_in[4];
  const float* ln_b   = (const float*)d_in[5];
  const float* Wh     = (const float*)d_in[6];
  const float* bh     = (const float*)d_in[7];
  const float* Wqk    = (const float*)d_in[8];
  const float* bqk    = (const float*)d_in[9];
  const float* gamma  = (const float*)d_in[10];
  const float* beta   = (const float*)d_in[11];
  const float* relb   = (const float*)d_in[12];
  const float* Wo     = (const float*)d_in[13];
  const float* bo     = (const float*)d_in[14];
  const float* Wd     = (const float*)d_in[15];
  const float* bd     = (const float*)d_in[16];
  float* out = (float*)d_out;

  cudaFuncSetAttribute(attn_kernel, cudaFuncAttributeMaxDynamicSharedMemorySize, ATTN_SMEM);
  cudaFuncSetAttribute(lin_kernel,  cudaFuncAttributeMaxDynamicSharedMemorySize, LIN_SMEM);

  embed_kernel<<<TOK,256>>>(x, W_emb, b_emb, pos);
  for (int l=0;l<NLAYER;l++){
    ln_kernel<<<TOK,256>>>(ln_g + l*DIM, ln_b + l*DIM);
    sgemm_kernel<0><<<dim3(H2/64,  TOK/128), 256>>>(Wh  + (size_t)l*DIM*H2,  bh + l*H2);
    sgemm_kernel<1><<<dim3(QKD/64, TOK/128), 256>>>(Wqk + (size_t)l*DIM*QKD, bqk + l*QKD);
    bias_kernel<<<GRP,GRP>>>(relb + l*32);
    attn_kernel<<<dim3(4,NG,NBATCH),256,ATTN_SMEM>>>(gamma + l*256, beta + l*256);
    cumsum_kernel<<<dim3(128,NBATCH),256>>>();
    lin_kernel<<<dim3(16,NG,NBATCH),256,LIN_SMEM>>>(gamma + l*256, beta + l*256);
    sgemm_kernel<2><<<dim3(DIM/64, TOK/128), 256>>>(Wo + (size_t)l*HIDW*DIM, bo + l*DIM);
  }
  mean1_kernel<<<dim3(NG,NBATCH),256>>>();
  head_kernel<<<NBATCH,256>>>(Wd, bd, out);
}

// round 7
// speedup vs baseline: 1.1687x; 1.1687x over previous
#include <cuda_runtime.h>
#include <cuda_bf16.h>
#include <math.h>
#include <stdint.h>

#define TOK 32768      // B*N = 4*8192
#define DIM 256
#define HIDW 512
#define H2 1024
#define QKD 64
#define GRP 256
#define NG 32          // groups per sequence
#define NBATCH 4
#define NLAYER 8

// ---------------- scratch (device globals; identical set to round-0 pass) --
__device__ float g_h[TOK*DIM];
__device__ float g_nx[TOK*DIM];
__device__ float g_hid[TOK*H2];
__device__ float g_qk[TOK*QKD];
__device__ float g_quad[TOK*HIDW];
__device__ float g_kv[NBATCH*NG*QKD*HIDW];
__device__ float g_bias[GRP*GRP];
__device__ float g_part[NBATCH*NG*DIM];

__device__ __forceinline__ float siluf(float x){ return x/(1.0f+expf(-x)); }
// pack two floats into a bf16x2 (lo in low half, hi in high half)
__device__ __forceinline__ uint32_t bpack(float lo, float hi){
  uint32_t r; asm("cvt.rn.bf16x2.f32 %0, %1, %2;" : "=r"(r) : "f"(hi), "f"(lo));
  return r;
}

// ---------------- embed: h = x@W_emb + b_emb + pos ------------------------
__global__ void embed_kernel(const float* __restrict__ x, const float* __restrict__ W,
                             const float* __restrict__ be, const float* __restrict__ pos){
  int row = blockIdx.x;
  int n = row & 8191;
  int d = threadIdx.x;
  __shared__ float xs[8];
  if (d < 5) xs[d] = x[row*5+d];
  __syncthreads();
  float acc = be[d] + pos[n*DIM+d];
  #pragma unroll
  for (int k=0;k<5;k++) acc = fmaf(xs[k], W[k*DIM+d], acc);
  g_h[row*DIM+d] = acc;
}

// ---------------- layernorm ------------------------------------------------
__global__ void ln_kernel(const float* __restrict__ gl, const float* __restrict__ bl){
  int row = blockIdx.x, d = threadIdx.x;
  float v = g_h[row*DIM+d];
  __shared__ float red[8];
  float s = v;
  #pragma unroll
  for (int o=16;o>0;o>>=1) s += __shfl_xor_sync(0xffffffffu, s, o);
  if ((d&31)==0) red[d>>5] = s;
  __syncthreads();
  float tot = 0.f;
  #pragma unroll
  for (int i=0;i<8;i++) tot += red[i];
  float mu = tot * (1.0f/DIM);
  float dv = v - mu;
  __syncthreads();
  float sq = dv*dv;
  #pragma unroll
  for (int o=16;o>0;o>>=1) sq += __shfl_xor_sync(0xffffffffu, sq, o);
  if ((d&31)==0) red[d>>5] = sq;
  __syncthreads();
  float vt = 0.f;
  #pragma unroll
  for (int i=0;i<8;i++) vt += red[i];
  float var = vt*(1.0f/DIM);
  g_nx[row*DIM+d] = fmaf(dv*rsqrtf(var+1e-5f), gl[d], bl[d]);
}

// ---------------- split-bf16 tensor-core GEMM ------------------------------
// C = A@B via (Ahi+Alo)(Bhi+Blo) ~= Ahi*Bhi + Ahi*Blo + Alo*Bhi  (fp32 accum)
// MODE 0: g_hid = silu(g_nx @ Wh + bh)   [32768,256]x[256,1024]
// MODE 1: g_qk  = silu(g_nx @ Wqk + bqk) [32768,256]x[256,64]
// MODE 2: g_h  += g_quad @ Wo + bo       [32768,512]x[512,256]
// CTA tile 128x64, k-tile 32, 8 warps (4m x 2n), warp tile 32x32,
// mma.sync.m16n8k16.bf16. No cp.async, static smem, no extra globals.
#define ASTR 20
#define BSTR 20
#define BMMA(acc, a, b) \
  asm volatile("mma.sync.aligned.m16n8k16.row.col.f32.bf16.bf16.f32 " \
    "{%0,%1,%2,%3}, {%4,%5,%6,%7}, {%8,%9}, {%0,%1,%2,%3};\n" \
    : "+f"(acc[0]),"+f"(acc[1]),"+f"(acc[2]),"+f"(acc[3]) \
    : "r"(a[0]),"r"(a[1]),"r"(a[2]),"r"(a[3]), "r"(b[0]),"r"(b[1]))

template<int MODE>
__global__ void __launch_bounds__(256) mma_gemm(const float* __restrict__ Bw,
                                                const float* __restrict__ bias){
  constexpr int N  = (MODE==0)?H2:(MODE==1)?QKD:DIM;
  constexpr int K  = (MODE==2)?HIDW:DIM;
  constexpr int KT = K/32;

  const float* A = (MODE==2) ? g_quad : g_nx;
  float* C = (MODE==0) ? g_hid : (MODE==1) ? g_qk : g_h;

  __shared__ uint32_t Ahi[128*ASTR], Alo[128*ASTR];   // [m][k as bf16x2]
  __shared__ uint32_t Bhi[64*BSTR],  Blo[64*BSTR];    // [n][k as bf16x2]

  int tid = threadIdx.x;
  int warp = tid>>5, lane = tid&31;
  int gq = lane>>2, tig = lane&3;
  int wm = (warp>>1)*32, wn = (warp&1)*32;
  int m0 = blockIdx.y*128, n0 = blockIdx.x*64;

  int ar = tid>>3,  ac = (tid&7)*4;    // A: fp32 col
  int br = tid>>4,  bc = (tid&15)*4;   // B: k-row / n-col

  float acc[2][4][4];
  #pragma unroll
  for (int mt=0;mt<2;mt++)
    #pragma unroll
    for (int nt=0;nt<4;nt++)
      #pragma unroll
      for (int c=0;c<4;c++) acc[mt][nt][c]=0.f;

  unsigned short* BhiS = (unsigned short*)Bhi;
  unsigned short* BloS = (unsigned short*)Blo;

  for (int kt=0; kt<KT; kt++){
    __syncthreads();
    // stage A tile [128 x 32] fp32 -> hi/lo bf16 pairs
    #pragma unroll
    for (int i=0;i<4;i++){
      float4 v = *(const float4*)(A + (size_t)(m0+ar+32*i)*K + kt*32 + ac);
      uint32_t h01 = bpack(v.x, v.y);
      uint32_t h23 = bpack(v.z, v.w);
      float h0 = __uint_as_float(h01<<16);
      float h1 = __uint_as_float(h01 & 0xffff0000u);
      float h2 = __uint_as_float(h23<<16);
      float h3 = __uint_as_float(h23 & 0xffff0000u);
      uint32_t l01 = bpack(v.x-h0, v.y-h1);
      uint32_t l23 = bpack(v.z-h2, v.w-h3);
      int base = (ar+32*i)*ASTR + (tid&7)*2;
      Ahi[base]   = h01;  Ahi[base+1] = h23;
      Alo[base]   = l01;  Alo[base+1] = l23;
    }
    // stage B tile [32 x 64] transposed to [n][k], hi/lo bf16
    #pragma unroll
    for (int i=0;i<2;i++){
      int kl = br + 16*i;
      float4 v = *(const float4*)(Bw + (size_t)(kt*32+kl)*N + n0 + bc);
      float vv[4] = {v.x, v.y, v.z, v.w};
      #pragma unroll
      for (int j=0;j<4;j++){
        __nv_bfloat16 h = __float2bfloat16(vv[j]);
        unsigned short hb = __bfloat16_as_ushort(h);
        float hf = __uint_as_float(((uint32_t)hb)<<16);
        unsigned short lb = __bfloat16_as_ushort(__float2bfloat16(vv[j]-hf));
        BhiS[(bc+j)*(2*BSTR) + kl] = hb;
        BloS[(bc+j)*(2*BSTR) + kl] = lb;
      }
    }
    __syncthreads();

    #pragma unroll
    for (int kk=0;kk<2;kk++){
      uint32_t ah[2][4], al[2][4];
      #pragma unroll
      for (int mt=0;mt<2;mt++){
        int r0 = wm + mt*16 + gq;
        int c  = kk*8 + tig;
        ah[mt][0]=Ahi[ r0   *ASTR + c  ]; ah[mt][1]=Ahi[(r0+8)*ASTR + c  ];
        ah[mt][2]=Ahi[ r0   *ASTR + c+4]; ah[mt][3]=Ahi[(r0+8)*ASTR + c+4];
        al[mt][0]=Alo[ r0   *ASTR + c  ]; al[mt][1]=Alo[(r0+8)*ASTR + c  ];
        al[mt][2]=Alo[ r0   *ASTR + c+4]; al[mt][3]=Alo[(r0+8)*ASTR + c+4];
      }
      uint32_t bh[4][2], bl[4][2];
      #pragma unroll
      for (int nt=0;nt<4;nt++){
        int c0 = wn + nt*8 + gq;
        bh[nt][0]=Bhi[c0*BSTR + kk*8+tig]; bh[nt][1]=Bhi[c0*BSTR + kk*8+tig+4];
        bl[nt][0]=Blo[c0*BSTR + kk*8+tig]; bl[nt][1]=Blo[c0*BSTR + kk*8+tig+4];
      }
      #pragma unroll
      for (int mt=0;mt<2;mt++)
        #pragma unroll
        for (int nt=0;nt<4;nt++){
          BMMA(acc[mt][nt], ah[mt], bh[nt]);
          BMMA(acc[mt][nt], ah[mt], bl[nt]);
          BMMA(acc[mt][nt], al[mt], bh[nt]);
        }
    }
  }

  // epilogue
  #pragma unroll
  for (int mt=0;mt<2;mt++){
    int r0 = m0 + wm + mt*16 + gq;
    #pragma unroll
    for (int nt=0;nt<4;nt++){
      int c0 = n0 + wn + nt*8 + tig*2;
      float b0 = bias[c0], b1 = bias[c0+1];
      #pragma unroll
      for (int h=0;h<2;h++){
        int row = r0 + h*8;
        float v0 = acc[mt][nt][h*2+0] + b0;
        float v1 = acc[mt][nt][h*2+1] + b1;
        float* p = C + (size_t)row*N + c0;
        if (MODE==2){ p[0] += v0; p[1] += v1; }
        else        { p[0] = siluf(v0); p[1] = siluf(v1); }
      }
    }
  }
}

// ---------------- T5 rel-pos bias table ------------------------------------
__global__ void bias_kernel(const float* __restrict__ relb){
  int i = blockIdx.x, j = threadIdx.x;
  int n = i - j; if (n < 0) n = 0;
  int bucket;
  if (n < 16) bucket = n;
  else {
    float t = logf((float)n * (1.0f/16.0f)) * (16.0f / 2.0794415416798357f); // /log(8)
    int val = 16 + (int)t;
    bucket = val < 31 ? val : 31;
  }
  g_bias[i*GRP + j] = relb[bucket]*8.0f;   // * sqrt(QKD)
}

// ---------------- fused quad attention + K^T V -----------------------------
#define SQS 68
#define SAS 260
#define ATTN_SMEM ((256*SQS + 64*SQS + 64*SAS + 64*128 + 6*64)*4)

__global__ void __launch_bounds__(256) attn_kernel(const float* __restrict__ gamma,
                                                   const float* __restrict__ beta){
  extern __shared__ float sm[];
  float* sQK  = sm;                 // [256][68]  raw silu(qk)
  float* sQQ  = sQK + 256*SQS;      // [64][68]   quad queries (this i-tile)
  float* sAtt = sQQ + 64*SQS;       // [64][260]  laplace attn tile
  float* sV   = sAtt + 64*SAS;      // [64][128]  v chunk
  float* sG   = sV + 64*128;        // g0,b0,g2,b2,g3,b3 (6*64)
  int it = blockIdx.x, g = blockIdx.y, b = blockIdx.z;
  int tid = threadIdx.x;
  size_t base = (size_t)(b*NG + g)*GRP;

  #pragma unroll
  for (int i=0;i<16;i++){
    int idx = i*256+tid;
    int r = idx>>4, c4 = (idx&15)*4;
    *(float4*)&sQK[r*SQS + c4] = *(const float4*)(g_qk + (base+r)*QKD + c4);
  }
  if (tid < 64){
    sG[tid]     = gamma[tid];      sG[64+tid]  = beta[tid];        // head 0 (qq)
    sG[128+tid] = gamma[128+tid];  sG[192+tid] = beta[128+tid];    // head 2 (qk)
    sG[256+tid] = gamma[192+tid];  sG[320+tid] = beta[192+tid];    // head 3 (lk)
  }
  __syncthreads();
  #pragma unroll
  for (int i=0;i<16;i++){
    int idx = i*256+tid; int ii = idx>>6, d = idx&63;
    sQQ[ii*SQS+d] = fmaf(sQK[(it*64+ii)*SQS + d], sG[d], sG[64+d]);
  }
  __syncthreads();

  int ty = tid>>5, tx = tid&31;
  // phase A: sim = qq.qkk/256 + bias -> laplace -> causal mask
  {
    float acc[8][8];
    #pragma unroll
    for (int r=0;r<8;r++)
      #pragma unroll
      for (int c=0;c<8;c++) acc[r][c]=0.f;
    #pragma unroll 4
    for (int d=0; d<64; d++){
      float g2 = sG[128+d], b2 = sG[192+d];
      float a[8], kk[8];
      #pragma unroll
      for (int r=0;r<8;r++) a[r] = sQQ[(ty*8+r)*SQS + d];
      #pragma unroll
      for (int c=0;c<8;c++) kk[c] = fmaf(sQK[(tx + 32*c)*SQS + d], g2, b2);
      #pragma unroll
      for (int r=0;r<8;r++)
        #pragma unroll
        for (int c=0;c<8;c++) acc[r][c] = fmaf(a[r], kk[c], acc[r][c]);
    }
    #pragma unroll
    for (int r=0;r<8;r++){
      int ig = it*64 + ty*8 + r;
      #pragma unroll
      for (int c=0;c<8;c++){
        int j = tx + 32*c;
        float s = acc[r][c]*(1.0f/256.0f) + g_bias[ig*GRP + j];
        float at = (j <= ig) ? 0.5f*(1.0f + erff((s - 0.70710678f)*0.79788456f)) : 0.0f;
        sAtt[(ty*8+r)*SAS + j] = at;
      }
    }
  }

  float g3r[8], b3r[8];
  #pragma unroll
  for (int r=0;r<8;r++){ g3r[r]=sG[256+ty*8+r]; b3r[r]=sG[320+ty*8+r]; }

  // phase B: quad = attn @ v, plus (it==0) kv = lk^T v / 256
  for (int et=0; et<4; et++){
    float qacc[8][4], kvacc[8][4];
    #pragma unroll
    for (int r=0;r<8;r++)
      #pragma unroll
      for (int c=0;c<4;c++){ qacc[r][c]=0.f; kvacc[r][c]=0.f; }
    for (int jc=0;jc<4;jc++){
      __syncthreads();
      #pragma unroll
      for (int i=0;i<8;i++){
        int idx = i*256+tid;
        int r = idx>>5, c4 = (idx&31)*4;
        *(float4*)&sV[r*128+c4] = *(const float4*)(g_hid + (base + jc*64 + r)*H2 + et*128 + c4);
      }
      __syncthreads();
      #pragma unroll 2
      for (int jj=0;jj<64;jj++){
        int j = jc*64 + jj;
        float4 v4 = *(float4*)&sV[jj*128 + tx*4];
        float a[8];
        #pragma unroll
        for (int r=0;r<8;r++) a[r] = sAtt[(ty*8+r)*SAS + j];
        #pragma unroll
        for (int r=0;r<8;r++){
          qacc[r][0]=fmaf(a[r],v4.x,qacc[r][0]);
          qacc[r][1]=fmaf(a[r],v4.y,qacc[r][1]);
          qacc[r][2]=fmaf(a[r],v4.z,qacc[r][2]);
          qacc[r][3]=fmaf(a[r],v4.w,qacc[r][3]);
        }
        if (it==0){
          #pragma unroll
          for (int r=0;r<8;r++){
            float lk = fmaf(sQK[j*SQS + ty*8 + r], g3r[r], b3r[r]);
            kvacc[r][0]=fmaf(lk,v4.x,kvacc[r][0]);
            kvacc[r][1]=fmaf(lk,v4.y,kvacc[r][1]);
            kvacc[r][2]=fmaf(lk,v4.z,kvacc[r][2]);
            kvacc[r][3]=fmaf(lk,v4.w,kvacc[r][3]);
          }
        }
      }
    }
    #pragma unroll
    for (int r=0;r<8;r++){
      size_t row = base + it*64 + ty*8 + r;
      float4 o; o.x=qacc[r][0]; o.y=qacc[r][1]; o.z=qacc[r][2]; o.w=qacc[r][3];
      *(float4*)(g_quad + row*HIDW + et*128 + tx*4) = o;
    }
    if (it==0){
      #pragma unroll
      for (int r=0;r<8;r++){
        float4 o;
        o.x=kvacc[r][0]*(1.0f/256.0f); o.y=kvacc[r][1]*(1.0f/256.0f);
        o.z=kvacc[r][2]*(1.0f/256.0f); o.w=kvacc[r][3]*(1.0f/256.0f);
        *(float4*)(g_kv + ((size_t)(b*NG+g)*QKD + ty*8 + r)*HIDW + et*128 + tx*4) = o;
      }
    }
  }
}

// ---------------- exclusive cumsum of kv over groups (in place) ------------
__global__ void cumsum_kernel(){
  int b = blockIdx.y;
  int idx = blockIdx.x*256 + threadIdx.x;   // 0..32767 = d*512+e
  float acc = 0.f;
  #pragma unroll
  for (int g=0; g<NG; g++){
    size_t p = ((size_t)(b*NG+g))*(QKD*HIDW) + idx;
    float cur = g_kv[p];
    g_kv[p] = acc;
    acc += cur;
  }
}

// ---------------- linear attention + gated combine -------------------------
#define LIN_SMEM ((64*64 + 64*128 + 128)*4)
__global__ void __launch_bounds__(256) lin_kernel(const float* __restrict__ gamma,
                                                  const float* __restrict__ beta){
  extern __shared__ float sm[];
  float* sLQ  = sm;              // [64][64]
  float* sLKV = sLQ + 64*64;     // [64][128]
  float* sG1  = sLKV + 64*128;   // [64]
  float* sB1  = sG1 + 64;        // [64]
  int et = blockIdx.x & 3, it = blockIdx.x >> 2;
  int g = blockIdx.y, b = blockIdx.z;
  int tid = threadIdx.x, ty = tid>>5, tx = tid&31;
  size_t base = (size_t)(b*NG+g)*GRP;

  if (tid < 64){ sG1[tid]=gamma[64+tid]; sB1[tid]=beta[64+tid]; }   // head 1 (lq)
  #pragma unroll
  for (int i=0;i<4;i++){
    int idx = i*256+tid; int r = idx>>4, c4 = (idx&15)*4;
    *(float4*)&sLQ[r*64+c4] = *(const float4*)(g_qk + (base + it*64 + r)*QKD + c4);
  }
  #pragma unroll
  for (int i=0;i<8;i++){
    int idx=i*256+tid; int r=idx>>5, c4=(idx&31)*4;
    *(float4*)&sLKV[r*128+c4] = *(const float4*)(g_kv + ((size_t)(b*NG+g)*QKD + r)*HIDW + et*128 + c4);
  }
  __syncthreads();
  #pragma unroll
  for (int i=0;i<16;i++){
    int idx=i*256+tid; int r=idx>>6, d=idx&63;
    sLQ[r*64+d] = fmaf(sLQ[r*64+d], sG1[d], sB1[d]);
  }
  __syncthreads();

  float acc[8][4];
  #pragma unroll
  for (int r=0;r<8;r++){ acc[r][0]=0.f; acc[r][1]=0.f; acc[r][2]=0.f; acc[r][3]=0.f; }
  #pragma unroll 4
  for (int d=0; d<64; d++){
    float4 kv4 = *(float4*)&sLKV[d*128 + tx*4];
    float a[8];
    #pragma unroll
    for (int r=0;r<8;r++) a[r] = sLQ[(ty*8+r)*64 + d];
    #pragma unroll
    for (int r=0;r<8;r++){
      acc[r][0]=fmaf(a[r],kv4.x,acc[r][0]);
      acc[r][1]=fmaf(a[r],kv4.y,acc[r][1]);
      acc[r][2]=fmaf(a[r],kv4.z,acc[r][2]);
      acc[r][3]=fmaf(a[r],kv4.w,acc[r][3]);
    }
  }
  #pragma unroll
  for (int r=0;r<8;r++){
    size_t row = base + it*64 + ty*8 + r;
    int e = et*128 + tx*4;
    float4 q  = *(float4*)(g_quad + row*HIDW + e);
    float4 gt = *(float4*)(g_hid + row*H2 + HIDW + e);
    float4 o;
    o.x = gt.x*(q.x+acc[r][0]);
    o.y = gt.y*(q.y+acc[r][1]);
    o.z = gt.z*(q.z+acc[r][2]);
    o.w = gt.w*(q.w+acc[r][3]);
    *(float4*)(g_quad + row*HIDW + e) = o;
  }
}

// ---------------- final mean pool + classifier -----------------------------
__global__ void mean1_kernel(){
  int c = blockIdx.x, b = blockIdx.y, d = threadIdx.x;
  float s = 0.f;
  size_t rb = (size_t)b*8192 + (size_t)c*256;
  for (int r=0;r<256;r++) s += g_h[(rb+r)*DIM + d];
  g_part[(b*NG+c)*DIM + d] = s;
}

__global__ void head_kernel(const float* __restrict__ Wd, const float* __restrict__ bd,
                            float* __restrict__ out){
  int b = blockIdx.x, d = threadIdx.x;
  float s = 0.f;
  for (int c=0;c<NG;c++) s += g_part[(b*NG+c)*DIM + d];
  s *= (1.0f/8192.0f);
  __shared__ float r0[256], r1[256];
  r0[d] = s*Wd[d*2+0];
  r1[d] = s*Wd[d*2+1];
  __syncthreads();
  for (int o=128;o>0;o>>=1){
    if (d<o){ r0[d]+=r0[d+o]; r1[d]+=r1[d+o]; }
    __syncthreads();
  }
  if (d==0){ out[b*2+0]=r0[0]+bd[0]; out[b*2+1]=r1[0]+bd[1]; }
}

// ---------------- host ------------------------------------------------------
extern "C" void kernel_launch(void* const* d_in, const int* in_sizes, int n_in,
                              void* d_out, int out_size){
  const float* x      = (const float*)d_in[0];
  const float* W_emb  = (const float*)d_in[1];
  const float* b_emb  = (const float*)d_in[2];
  const float* pos    = (const float*)d_in[3];
  const float* ln_g   = (const float*)d_in[4];
  const float* ln_b   = (const float*)d_in[5];
  const float* Wh     = (const float*)d_in[6];
  const float* bh     = (const float*)d_in[7];
  const float* Wqk    = (const float*)d_in[8];
  const float* bqk    = (const float*)d_in[9];
  const float* gamma  = (const float*)d_in[10];
  const float* beta   = (const float*)d_in[11];
  const float* relb   = (const float*)d_in[12];
  const float* Wo     = (const float*)d_in[13];
  const float* bo     = (const float*)d_in[14];
  const float* Wd     = (const float*)d_in[15];
  const float* bd     = (const float*)d_in[16];
  float* out = (float*)d_out;

  cudaFuncSetAttribute(attn_kernel, cudaFuncAttributeMaxDynamicSharedMemorySize, ATTN_SMEM);
  cudaFuncSetAttribute(lin_kernel,  cudaFuncAttributeMaxDynamicSharedMemorySize, LIN_SMEM);

  embed_kernel<<<TOK,256>>>(x, W_emb, b_emb, pos);
  for (int l=0;l<NLAYER;l++){
    ln_kernel<<<TOK,256>>>(ln_g + l*DIM, ln_b + l*DIM);
    mma_gemm<0><<<dim3(H2/64,  TOK/128), 256>>>(Wh  + (size_t)l*DIM*H2,  bh + l*H2);
    mma_gemm<1><<<dim3(QKD/64, TOK/128), 256>>>(Wqk + (size_t)l*DIM*QKD, bqk + l*QKD);
    bias_kernel<<<GRP,GRP>>>(relb + l*32);
    attn_kernel<<<dim3(4,NG,NBATCH),256,ATTN_SMEM>>>(gamma + l*256, beta + l*256);
    cumsum_kernel<<<dim3(128,NBATCH),256>>>();
    lin_kernel<<<dim3(16,NG,NBATCH),256,LIN_SMEM>>>(gamma + l*256, beta + l*256);
    mma_gemm<2><<<dim3(DIM/64, TOK/128), 256>>>(Wo + (size_t)l*HIDW*DIM, bo + l*DIM);
  }
  mean1_kernel<<<dim3(NG,NBATCH),256>>>();
  head_kernel<<<NBATCH,256>>>(Wd, bd, out);
}

// round 9
// speedup vs baseline: 1.2675x; 1.0845x over previous
#include <cuda_runtime.h>
#include <cuda_bf16.h>
#include <math.h>
#include <stdint.h>

#define TOK 32768      // B*N = 4*8192
#define DIM 256
#define HIDW 512
#define H2 1024
#define QKD 64
#define GRP 256
#define NG 32          // groups per sequence
#define NBATCH 4
#define NLAYER 8
#define WLAYER (DIM*H2 + DIM*QKD + HIDW*DIM)   // 409600
#define WTOT (NLAYER*WLAYER)

// ---------------- scratch (device globals only; no allocation) -------------
__device__ float g_h[TOK*DIM];
__device__ float g_hid[TOK*H2];
__device__ float g_qk[TOK*QKD];
__device__ float g_quad[TOK*HIDW];
__device__ float g_kv[NBATCH*NG*QKD*HIDW];
__device__ float g_bias[GRP*GRP];
__device__ float g_part[NBATCH*NG*DIM];
// pre-split bf16 operands
__device__ __nv_bfloat16 g_axh[TOK*DIM],  g_axl[TOK*DIM];    // ln output
__device__ __nv_bfloat16 g_aqh[TOK*HIDW], g_aql[TOK*HIDW];   // gated quad+lin
__device__ __nv_bfloat16 g_wh[WTOT], g_wl[WTOT];             // transposed weights [n][k]

__device__ __forceinline__ float siluf(float x){ return x/(1.0f+expf(-x)); }

// ---------------- weight prep: transpose + split to bf16 hi/lo ------------
// W [K][N] row-major -> out [N][K] hi/lo
__global__ void wprep_kernel(const float* __restrict__ W, int woff, int K, int N){
  __shared__ float t[32][33];
  int n0 = blockIdx.x*32, k0 = blockIdx.y*32;
  int tx = threadIdx.x, ty = threadIdx.y;   // 32 x 8
  #pragma unroll
  for (int i=0;i<32;i+=8)
    t[ty+i][tx] = W[(size_t)(k0+ty+i)*N + n0+tx];
  __syncthreads();
  #pragma unroll
  for (int i=0;i<32;i+=8){
    float v = t[tx][ty+i];
    __nv_bfloat16 h = __float2bfloat16(v);
    float hf = __bfloat162float(h);
    size_t o = (size_t)woff + (size_t)(n0+ty+i)*K + k0+tx;
    g_wh[o] = h;
    g_wl[o] = __float2bfloat16(v - hf);
  }
}

// ---------------- embed: h = x@W_emb + b_emb + pos ------------------------
__global__ void embed_kernel(const float* __restrict__ x, const float* __restrict__ W,
                             const float* __restrict__ be, const float* __restrict__ pos){
  int row = blockIdx.x;
  int n = row & 8191;
  int d = threadIdx.x;
  __shared__ float xs[8];
  if (d < 5) xs[d] = x[row*5+d];
  __syncthreads();
  float acc = be[d] + pos[n*DIM+d];
  #pragma unroll
  for (int k=0;k<5;k++) acc = fmaf(xs[k], W[k*DIM+d], acc);
  g_h[row*DIM+d] = acc;
}

// ---------------- layernorm (writes pre-split bf16 hi/lo) ------------------
__global__ void ln_kernel(const float* __restrict__ gl, const float* __restrict__ bl){
  int row = blockIdx.x, d = threadIdx.x;
  float v = g_h[row*DIM+d];
  __shared__ float red[8];
  float s = v;
  #pragma unroll
  for (int o=16;o>0;o>>=1) s += __shfl_xor_sync(0xffffffffu, s, o);
  if ((d&31)==0) red[d>>5] = s;
  __syncthreads();
  float tot = 0.f;
  #pragma unroll
  for (int i=0;i<8;i++) tot += red[i];
  float mu = tot * (1.0f/DIM);
  float dv = v - mu;
  __syncthreads();
  float sq = dv*dv;
  #pragma unroll
  for (int o=16;o>0;o>>=1) sq += __shfl_xor_sync(0xffffffffu, sq, o);
  if ((d&31)==0) red[d>>5] = sq;
  __syncthreads();
  float vt = 0.f;
  #pragma unroll
  for (int i=0;i<8;i++) vt += red[i];
  float var = vt*(1.0f/DIM);
  float y = fmaf(dv*rsqrtf(var+1e-5f), gl[d], bl[d]);
  __nv_bfloat16 h = __float2bfloat16(y);
  g_axh[row*DIM+d] = h;
  g_axl[row*DIM+d] = __float2bfloat16(y - __bfloat162float(h));
}

// ---------------- split-bf16 tensor-core GEMM (pipelined) ------------------
// C = A@B via Ahi*Bhi + Ahi*Blo + Alo*Bhi (fp32 accum)
// MODE 0: g_hid = silu(nx @ Wh + bh)    [32768,256]x[256,1024]
// MODE 1: g_qk  = silu(nx @ Wqk + bqk)  [32768,256]x[256,64]
// MODE 2: g_h  += quad @ Wo + bo        [32768,512]x[512,256]
// CTA 128x64, k-tile 32, 8 warps (4m x 2n), double-buffered smem +
// register prefetch, one __syncthreads per k-tile. No cp.async.
#define ABUF 2560   // 128*20 u32
#define BBUF 1280   // 64*20 u32
#define GSM ((2*ABUF*2 + 2*BBUF*2)*4)  // 61440 bytes

#define BMMA(acc, a, b) \
  asm volatile("mma.sync.aligned.m16n8k16.row.col.f32.bf16.bf16.f32 " \
    "{%0,%1,%2,%3}, {%4,%5,%6,%7}, {%8,%9}, {%0,%1,%2,%3};\n" \
    : "+f"(acc[0]),"+f"(acc[1]),"+f"(acc[2]),"+f"(acc[3]) \
    : "r"(a[0]),"r"(a[1]),"r"(a[2]),"r"(a[3]), "r"(b[0]),"r"(b[1]))

#define LDTILE(kt) do{ \
  size_t ko = (size_t)(kt)*32 + ac; \
  pah[0] = *(const uint4*)(Ah + (size_t)(m0+ar0)*K + ko); \
  pal[0] = *(const uint4*)(Al + (size_t)(m0+ar0)*K + ko); \
  pah[1] = *(const uint4*)(Ah + (size_t)(m0+ar0+64)*K + ko); \
  pal[1] = *(const uint4*)(Al + (size_t)(m0+ar0+64)*K + ko); \
  pbh    = *(const uint4*)(Bh_ + (size_t)(n0+ar0)*K + ko); \
  pbl    = *(const uint4*)(Bl_ + (size_t)(n0+ar0)*K + ko); \
}while(0)

#define STTILE(buf) do{ \
  uint32_t* d0=&AH[(buf)*ABUF + ar0*20 + acu]; \
  d0[0]=pah[0].x; d0[1]=pah[0].y; d0[2]=pah[0].z; d0[3]=pah[0].w; \
  uint32_t* d1=&AL[(buf)*ABUF + ar0*20 + acu]; \
  d1[0]=pal[0].x; d1[1]=pal[0].y; d1[2]=pal[0].z; d1[3]=pal[0].w; \
  uint32_t* d2=&AH[(buf)*ABUF + (ar0+64)*20 + acu]; \
  d2[0]=pah[1].x; d2[1]=pah[1].y; d2[2]=pah[1].z; d2[3]=pah[1].w; \
  uint32_t* d3=&AL[(buf)*ABUF + (ar0+64)*20 + acu]; \
  d3[0]=pal[1].x; d3[1]=pal[1].y; d3[2]=pal[1].z; d3[3]=pal[1].w; \
  uint32_t* d4=&BH[(buf)*BBUF + ar0*20 + acu]; \
  d4[0]=pbh.x; d4[1]=pbh.y; d4[2]=pbh.z; d4[3]=pbh.w; \
  uint32_t* d5=&BL[(buf)*BBUF + ar0*20 + acu]; \
  d5[0]=pbl.x; d5[1]=pbl.y; d5[2]=pbl.z; d5[3]=pbl.w; \
}while(0)

template<int MODE>
__global__ void __launch_bounds__(256) mma_gemm(int woff, const float* __restrict__ bias){
  constexpr int N  = (MODE==0)?H2:(MODE==1)?QKD:DIM;
  constexpr int K  = (MODE==2)?HIDW:DIM;
  constexpr int KT = K/32;

  const __nv_bfloat16* Ah = (MODE==2)? g_aqh : g_axh;
  const __nv_bfloat16* Al = (MODE==2)? g_aql : g_axl;
  const __nv_bfloat16* Bh_ = g_wh + woff;
  const __nv_bfloat16* Bl_ = g_wl + woff;
  float* C = (MODE==0) ? g_hid : (MODE==1) ? g_qk : g_h;

  extern __shared__ uint32_t smu[];
  uint32_t* AH = smu;
  uint32_t* AL = smu + 2*ABUF;
  uint32_t* BH = smu + 4*ABUF;
  uint32_t* BL = smu + 4*ABUF + 2*BBUF;

  int tid = threadIdx.x;
  int warp = tid>>5, lane = tid&31;
  int gq = lane>>2, tig = lane&3;
  int wm = (warp>>1)*32, wn = (warp&1)*32;
  int m0 = blockIdx.y*128, n0 = blockIdx.x*64;

  int ar0 = tid>>2;            // A rows ar0, ar0+64; B row ar0 (0..63)
  int ac  = (tid&3)*8;         // bf16 col within k-tile
  int acu = (tid&3)*4;         // u32 col

  float acc[2][4][4];
  #pragma unroll
  for (int mt=0;mt<2;mt++)
    #pragma unroll
    for (int nt=0;nt<4;nt++)
      #pragma unroll
      for (int c=0;c<4;c++) acc[mt][nt][c]=0.f;

  uint4 pah[2], pal[2], pbh, pbl;

  LDTILE(0);
  STTILE(0);
  __syncthreads();

  for (int kt=0; kt<KT; kt++){
    int buf = kt&1;
    if (kt+1 < KT) LDTILE(kt+1);

    const uint32_t* ah_ = &AH[buf*ABUF];
    const uint32_t* al_ = &AL[buf*ABUF];
    const uint32_t* bhp = &BH[buf*BBUF];
    const uint32_t* blp = &BL[buf*BBUF];
    #pragma unroll
    for (int kk=0;kk<2;kk++){
      uint32_t ahf[2][4], alf[2][4];
      #pragma unroll
      for (int mt=0;mt<2;mt++){
        int r0 = wm + mt*16 + gq;
        int c  = kk*8 + tig;
        ahf[mt][0]=ah_[ r0   *20 + c  ]; ahf[mt][1]=ah_[(r0+8)*20 + c  ];
        ahf[mt][2]=ah_[ r0   *20 + c+4]; ahf[mt][3]=ah_[(r0+8)*20 + c+4];
        alf[mt][0]=al_[ r0   *20 + c  ]; alf[mt][1]=al_[(r0+8)*20 + c  ];
        alf[mt][2]=al_[ r0   *20 + c+4]; alf[mt][3]=al_[(r0+8)*20 + c+4];
      }
      uint32_t bhf[4][2], blf[4][2];
      #pragma unroll
      for (int nt=0;nt<4;nt++){
        int c0 = wn + nt*8 + gq;
        bhf[nt][0]=bhp[c0*20 + kk*8+tig]; bhf[nt][1]=bhp[c0*20 + kk*8+tig+4];
        blf[nt][0]=blp[c0*20 + kk*8+tig]; blf[nt][1]=blp[c0*20 + kk*8+tig+4];
      }
      #pragma unroll
      for (int mt=0;mt<2;mt++)
        #pragma unroll
        for (int nt=0;nt<4;nt++){
          BMMA(acc[mt][nt], ahf[mt], bhf[nt]);
          BMMA(acc[mt][nt], ahf[mt], blf[nt]);
          BMMA(acc[mt][nt], alf[mt], bhf[nt]);
        }
    }
    if (kt+1 < KT) STTILE(buf^1);
    __syncthreads();
  }

  // epilogue
  #pragma unroll
  for (int mt=0;mt<2;mt++){
    int r0 = m0 + wm + mt*16 + gq;
    #pragma unroll
    for (int nt=0;nt<4;nt++){
      int c0 = n0 + wn + nt*8 + tig*2;
      float b0 = bias[c0], b1 = bias[c0+1];
      #pragma unroll
      for (int h=0;h<2;h++){
        int row = r0 + h*8;
        float v0 = acc[mt][nt][h*2+0] + b0;
        float v1 = acc[mt][nt][h*2+1] + b1;
        float* p = C + (size_t)row*N + c0;
        if (MODE==2){ p[0] += v0; p[1] += v1; }
        else        { p[0] = siluf(v0); p[1] = siluf(v1); }
      }
    }
  }
}

// ---------------- T5 rel-pos bias table ------------------------------------
__global__ void bias_kernel(const float* __restrict__ relb){
  int i = blockIdx.x, j = threadIdx.x;
  int n = i - j; if (n < 0) n = 0;
  int bucket;
  if (n < 16) bucket = n;
  else {
    float t = logf((float)n * (1.0f/16.0f)) * (16.0f / 2.0794415416798357f); // /log(8)
    int val = 16 + (int)t;
    bucket = val < 31 ? val : 31;
  }
  g_bias[i*GRP + j] = relb[bucket]*8.0f;   // * sqrt(QKD)
}

// ---------------- fused quad attention + K^T V -----------------------------
#define SQS 68
#define SAS 260
#define ATTN_SMEM ((256*SQS + 64*SQS + 64*SAS + 64*128 + 6*64)*4)

__global__ void __launch_bounds__(256) attn_kernel(const float* __restrict__ gamma,
                                                   const float* __restrict__ beta){
  extern __shared__ float sm[];
  float* sQK  = sm;                 // [256][68]  raw silu(qk)
  float* sQQ  = sQK + 256*SQS;      // [64][68]   quad queries (this i-tile)
  float* sAtt = sQQ + 64*SQS;       // [64][260]  laplace attn tile
  float* sV   = sAtt + 64*SAS;      // [64][128]  v chunk
  float* sG   = sV + 64*128;        // g0,b0,g2,b2,g3,b3 (6*64)
  int it = blockIdx.x, g = blockIdx.y, b = blockIdx.z;
  int tid = threadIdx.x;
  size_t base = (size_t)(b*NG + g)*GRP;

  #pragma unroll
  for (int i=0;i<16;i++){
    int idx = i*256+tid;
    int r = idx>>4, c4 = (idx&15)*4;
    *(float4*)&sQK[r*SQS + c4] = *(const float4*)(g_qk + (base+r)*QKD + c4);
  }
  if (tid < 64){
    sG[tid]     = gamma[tid];      sG[64+tid]  = beta[tid];        // head 0 (qq)
    sG[128+tid] = gamma[128+tid];  sG[192+tid] = beta[128+tid];    // head 2 (qk)
    sG[256+tid] = gamma[192+tid];  sG[320+tid] = beta[192+tid];    // head 3 (lk)
  }
  __syncthreads();
  #pragma unroll
  for (int i=0;i<16;i++){
    int idx = i*256+tid; int ii = idx>>6, d = idx&63;
    sQQ[ii*SQS+d] = fmaf(sQK[(it*64+ii)*SQS + d], sG[d], sG[64+d]);
  }
  __syncthreads();

  int ty = tid>>5, tx = tid&31;
  // phase A: sim = qq.qkk/256 + bias -> laplace -> causal mask
  {
    float acc[8][8];
    #pragma unroll
    for (int r=0;r<8;r++)
      #pragma unroll
      for (int c=0;c<8;c++) acc[r][c]=0.f;
    #pragma unroll 4
    for (int d=0; d<64; d++){
      float g2 = sG[128+d], b2 = sG[192+d];
      float a[8], kk[8];
      #pragma unroll
      for (int r=0;r<8;r++) a[r] = sQQ[(ty*8+r)*SQS + d];
      #pragma unroll
      for (int c=0;c<8;c++) kk[c] = fmaf(sQK[(tx + 32*c)*SQS + d], g2, b2);
      #pragma unroll
      for (int r=0;r<8;r++)
        #pragma unroll
        for (int c=0;c<8;c++) acc[r][c] = fmaf(a[r], kk[c], acc[r][c]);
    }
    #pragma unroll
    for (int r=0;r<8;r++){
      int ig = it*64 + ty*8 + r;
      #pragma unroll
      for (int c=0;c<8;c++){
        int j = tx + 32*c;
        float s = acc[r][c]*(1.0f/256.0f) + g_bias[ig*GRP + j];
        float at = (j <= ig) ? 0.5f*(1.0f + erff((s - 0.70710678f)*0.79788456f)) : 0.0f;
        sAtt[(ty*8+r)*SAS + j] = at;
      }
    }
  }

  float g3r[8], b3r[8];
  #pragma unroll
  for (int r=0;r<8;r++){ g3r[r]=sG[256+ty*8+r]; b3r[r]=sG[320+ty*8+r]; }

  // phase B: quad = attn @ v, plus (it==0) kv = lk^T v / 256
  for (int et=0; et<4; et++){
    float qacc[8][4], kvacc[8][4];
    #pragma unroll
    for (int r=0;r<8;r++)
      #pragma unroll
      for (int c=0;c<4;c++){ qacc[r][c]=0.f; kvacc[r][c]=0.f; }
    for (int jc=0;jc<4;jc++){
      __syncthreads();
      #pragma unroll
      for (int i=0;i<8;i++){
        int idx = i*256+tid;
        int r = idx>>5, c4 = (idx&31)*4;
        *(float4*)&sV[r*128+c4] = *(const float4*)(g_hid + (base + jc*64 + r)*H2 + et*128 + c4);
      }
      __syncthreads();
      #pragma unroll 2
      for (int jj=0;jj<64;jj++){
        int j = jc*64 + jj;
        float4 v4 = *(float4*)&sV[jj*128 + tx*4];
        float a[8];
        #pragma unroll
        for (int r=0;r<8;r++) a[r] = sAtt[(ty*8+r)*SAS + j];
        #pragma unroll
        for (int r=0;r<8;r++){
          qacc[r][0]=fmaf(a[r],v4.x,qacc[r][0]);
          qacc[r][1]=fmaf(a[r],v4.y,qacc[r][1]);
          qacc[r][2]=fmaf(a[r],v4.z,qacc[r][2]);
          qacc[r][3]=fmaf(a[r],v4.w,qacc[r][3]);
        }
        if (it==0){
          #pragma unroll
          for (int r=0;r<8;r++){
            float lk = fmaf(sQK[j*SQS + ty*8 + r], g3r[r], b3r[r]);
            kvacc[r][0]=fmaf(lk,v4.x,kvacc[r][0]);
            kvacc[r][1]=fmaf(lk,v4.y,kvacc[r][1]);
            kvacc[r][2]=fmaf(lk,v4.z,kvacc[r][2]);
            kvacc[r][3]=fmaf(lk,v4.w,kvacc[r][3]);
          }
        }
      }
    }
    #pragma unroll
    for (int r=0;r<8;r++){
      size_t row = base + it*64 + ty*8 + r;
      float4 o; o.x=qacc[r][0]; o.y=qacc[r][1]; o.z=qacc[r][2]; o.w=qacc[r][3];
      *(float4*)(g_quad + row*HIDW + et*128 + tx*4) = o;
    }
    if (it==0){
      #pragma unroll
      for (int r=0;r<8;r++){
        float4 o;
        o.x=kvacc[r][0]*(1.0f/256.0f); o.y=kvacc[r][1]*(1.0f/256.0f);
        o.z=kvacc[r][2]*(1.0f/256.0f); o.w=kvacc[r][3]*(1.0f/256.0f);
        *(float4*)(g_kv + ((size_t)(b*NG+g)*QKD + ty*8 + r)*HIDW + et*128 + tx*4) = o;
      }
    }
  }
}

// ---------------- exclusive cumsum of kv over groups (in place) ------------
__global__ void cumsum_kernel(){
  int b = blockIdx.y;
  int idx = blockIdx.x*256 + threadIdx.x;   // 0..32767 = d*512+e
  float acc = 0.f;
  #pragma unroll
  for (int g=0; g<NG; g++){
    size_t p = ((size_t)(b*NG+g))*(QKD*HIDW) + idx;
    float cur = g_kv[p];
    g_kv[p] = acc;
    acc += cur;
  }
}

// ---------------- linear attention + gated combine (writes bf16 splits) ----
#define LIN_SMEM ((64*64 + 64*128 + 128)*4)
__global__ void __launch_bounds__(256) lin_kernel(const float* __restrict__ gamma,
                                                  const float* __restrict__ beta){
  extern __shared__ float sm[];
  float* sLQ  = sm;              // [64][64]
  float* sLKV = sLQ + 64*64;     // [64][128]
  float* sG1  = sLKV + 64*128;   // [64]
  float* sB1  = sG1 + 64;        // [64]
  int et = blockIdx.x & 3, it = blockIdx.x >> 2;
  int g = blockIdx.y, b = blockIdx.z;
  int tid = threadIdx.x, ty = tid>>5, tx = tid&31;
  size_t base = (size_t)(b*NG+g)*GRP;

  if (tid < 64){ sG1[tid]=gamma[64+tid]; sB1[tid]=beta[64+tid]; }   // head 1 (lq)
  #pragma unroll
  for (int i=0;i<4;i++){
    int idx = i*256+tid; int r = idx>>4, c4 = (idx&15)*4;
    *(float4*)&sLQ[r*64+c4] = *(const float4*)(g_qk + (base + it*64 + r)*QKD + c4);
  }
  #pragma unroll
  for (int i=0;i<8;i++){
    int idx=i*256+tid; int r=idx>>5, c4=(idx&31)*4;
    *(float4*)&sLKV[r*128+c4] = *(const float4*)(g_kv + ((size_t)(b*NG+g)*QKD + r)*HIDW + et*128 + c4);
  }
  __syncthreads();
  #pragma unroll
  for (int i=0;i<16;i++){
    int idx=i*256+tid; int r=idx>>6, d=idx&63;
    sLQ[r*64+d] = fmaf(sLQ[r*64+d], sG1[d], sB1[d]);
  }
  __syncthreads();

  float acc[8][4];
  #pragma unroll
  for (int r=0;r<8;r++){ acc[r][0]=0.f; acc[r][1]=0.f; acc[r][2]=0.f; acc[r][3]=0.f; }
  #pragma unroll 4
  for (int d=0; d<64; d++){
    float4 kv4 = *(float4*)&sLKV[d*128 + tx*4];
    float a[8];
    #pragma unroll
    for (int r=0;r<8;r++) a[r] = sLQ[(ty*8+r)*64 + d];
    #pragma unroll
    for (int r=0;r<8;r++){
      acc[r][0]=fmaf(a[r],kv4.x,acc[r][0]);
      acc[r][1]=fmaf(a[r],kv4.y,acc[r][1]);
      acc[r][2]=fmaf(a[r],kv4.z,acc[r][2]);
      acc[r][3]=fmaf(a[r],kv4.w,acc[r][3]);
    }
  }
  #pragma unroll
  for (int r=0;r<8;r++){
    size_t row = base + it*64 + ty*8 + r;
    int e = et*128 + tx*4;
    float4 q  = *(float4*)(g_quad + row*HIDW + e);
    float4 gt = *(float4*)(g_hid + row*H2 + HIDW + e);
    float o[4];
    o[0] = gt.x*(q.x+acc[r][0]);
    o[1] = gt.y*(q.y+acc[r][1]);
    o[2] = gt.z*(q.z+acc[r][2]);
    o[3] = gt.w*(q.w+acc[r][3]);
    size_t p = row*HIDW + e;
    #pragma unroll
    for (int c=0;c<4;c++){
      __nv_bfloat16 h = __float2bfloat16(o[c]);
      g_aqh[p+c] = h;
      g_aql[p+c] = __float2bfloat16(o[c] - __bfloat162float(h));
    }
  }
}

// ---------------- final mean pool + classifier -----------------------------
__global__ void mean1_kernel(){
  int c = blockIdx.x, b = blockIdx.y, d = threadIdx.x;
  float s = 0.f;
  size_t rb = (size_t)b*8192 + (size_t)c*256;
  for (int r=0;r<256;r++) s += g_h[(rb+r)*DIM + d];
  g_part[(b*NG+c)*DIM + d] = s;
}

__global__ void head_kernel(const float* __restrict__ Wd, const float* __restrict__ bd,
                            float* __restrict__ out){
  int b = blockIdx.x, d = threadIdx.x;
  float s = 0.f;
  for (int c=0;c<NG;c++) s += g_part[(b*NG+c)*DIM + d];
  s *= (1.0f/8192.0f);
  __shared__ float r0[256], r1[256];
  r0[d] = s*Wd[d*2+0];
  r1[d] = s*Wd[d*2+1];
  __syncthreads();
  for (int o=128;o>0;o>>=1){
    if (d<o){ r0[d]+=r0[d+o]; r1[d]+=r1[d+o]; }
    __syncthreads();
  }
  if (d==0){ out[b*2+0]=r0[0]+bd[0]; out[b*2+1]=r1[0]+bd[1]; }
}

// ---------------- host ------------------------------------------------------
extern "C" void kernel_launch(void* const* d_in, const int* in_sizes, int n_in,
                              void* d_out, int out_size){
  const float* x      = (const float*)d_in[0];
  const float* W_emb  = (const float*)d_in[1];
  const float* b_emb  = (const float*)d_in[2];
  const float* pos    = (const float*)d_in[3];
  const float* ln_g   = (const float*)d_in[4];
  const float* ln_b   = (const float*)d_in[5];
  const float* Wh     = (const float*)d_in[6];
  const float* bh     = (const float*)d_in[7];
  const float* Wqk    = (const float*)d_in[8];
  const float* bqk    = (const float*)d_in[9];
  const float* gamma  = (const float*)d_in[10];
  const float* beta   = (const float*)d_in[11];
  const float* relb   = (const float*)d_in[12];
  const float* Wo     = (const float*)d_in[13];
  const float* bo     = (const float*)d_in[14];
  const float* Wd     = (const float*)d_in[15];
  const float* bd     = (const float*)d_in[16];
  float* out = (float*)d_out;

  cudaFuncSetAttribute(attn_kernel, cudaFuncAttributeMaxDynamicSharedMemorySize, ATTN_SMEM);
  cudaFuncSetAttribute(lin_kernel,  cudaFuncAttributeMaxDynamicSharedMemorySize, LIN_SMEM);
  cudaFuncSetAttribute(mma_gemm<0>, cudaFuncAttributeMaxDynamicSharedMemorySize, GSM);
  cudaFuncSetAttribute(mma_gemm<1>, cudaFuncAttributeMaxDynamicSharedMemorySize, GSM);
  cudaFuncSetAttribute(mma_gemm<2>, cudaFuncAttributeMaxDynamicSharedMemorySize, GSM);

  // weight prep (transpose + split) for all layers
  for (int l=0;l<NLAYER;l++){
    int base = l*WLAYER;
    wprep_kernel<<<dim3(H2/32,  DIM/32),  dim3(32,8)>>>(Wh  + (size_t)l*DIM*H2,  base,                    DIM,  H2);
    wprep_kernel<<<dim3(QKD/32, DIM/32),  dim3(32,8)>>>(Wqk + (size_t)l*DIM*QKD, base + DIM*H2,           DIM,  QKD);
    wprep_kernel<<<dim3(DIM/32, HIDW/32), dim3(32,8)>>>(Wo  + (size_t)l*HIDW*DIM,base + DIM*H2 + DIM*QKD, HIDW, DIM);
  }

  embed_kernel<<<TOK,256>>>(x, W_emb, b_emb, pos);
  for (int l=0;l<NLAYER;l++){
    int base = l*WLAYER;
    ln_kernel<<<TOK,256>>>(ln_g + l*DIM, ln_b + l*DIM);
    mma_gemm<0><<<dim3(H2/64,  TOK/128), 256, GSM>>>(base,                    bh  + l*H2);
    mma_gemm<1><<<dim3(QKD/64, TOK/128), 256, GSM>>>(base + DIM*H2,           bqk + l*QKD);
    bias_kernel<<<GRP,GRP>>>(relb + l*32);
    attn_kernel<<<dim3(4,NG,NBATCH),256,ATTN_SMEM>>>(gamma + l*256, beta + l*256);
    cumsum_kernel<<<dim3(128,NBATCH),256>>>();
    lin_kernel<<<dim3(16,NG,NBATCH),256,LIN_SMEM>>>(gamma + l*256, beta + l*256);
    mma_gemm<2><<<dim3(DIM/64, TOK/128), 256, GSM>>>(base + DIM*H2 + DIM*QKD, bo  + l*DIM);
  }
  mean1_kernel<<<dim3(NG,NBATCH),256>>>();
  head_kernel<<<NBATCH,256>>>(Wd, bd, out);
}

// round 10
// speedup vs baseline: 1.2935x; 1.0205x over previous
#include <cuda_runtime.h>
#include <cuda_bf16.h>
#include <math.h>
#include <stdint.h>

#define TOK 32768      // B*N = 4*8192
#define DIM 256
#define HIDW 512
#define H2 1024
#define QKD 64
#define GRP 256
#define NG 32          // groups per sequence
#define NBATCH 4
#define NLAYER 8
#define WLAYER (DIM*H2 + DIM*QKD + HIDW*DIM)   // 409600
#define WTOT (NLAYER*WLAYER)

// ---------------- scratch (device globals only; no allocation) -------------
__device__ float g_h[TOK*DIM];
__device__ float g_hid[TOK*H2];
__device__ float g_qk[TOK*QKD];
__device__ float g_quad[TOK*HIDW];
__device__ float g_kv[NBATCH*NG*QKD*HIDW];
__device__ float g_bias[GRP*GRP];
__device__ float g_part[NBATCH*NG*DIM];
// pre-split bf16 operands
__device__ __nv_bfloat16 g_axh[TOK*DIM],  g_axl[TOK*DIM];    // ln output
__device__ __nv_bfloat16 g_aqh[TOK*HIDW], g_aql[TOK*HIDW];   // gated quad+lin
__device__ __nv_bfloat16 g_wh[WTOT], g_wl[WTOT];             // transposed weights [n][k]

__device__ __forceinline__ float siluf(float x){ return x/(1.0f+expf(-x)); }

// ---------------- weight prep: transpose + split to bf16 hi/lo ------------
// W [K][N] row-major -> out [N][K] hi/lo
__global__ void wprep_kernel(const float* __restrict__ W, int woff, int K, int N){
  __shared__ float t[32][33];
  int n0 = blockIdx.x*32, k0 = blockIdx.y*32;
  int tx = threadIdx.x, ty = threadIdx.y;   // 32 x 8
  #pragma unroll
  for (int i=0;i<32;i+=8)
    t[ty+i][tx] = W[(size_t)(k0+ty+i)*N + n0+tx];
  __syncthreads();
  #pragma unroll
  for (int i=0;i<32;i+=8){
    float v = t[tx][ty+i];
    __nv_bfloat16 h = __float2bfloat16(v);
    float hf = __bfloat162float(h);
    size_t o = (size_t)woff + (size_t)(n0+ty+i)*K + k0+tx;
    g_wh[o] = h;
    g_wl[o] = __float2bfloat16(v - hf);
  }
}

// ---------------- embed: h = x@W_emb + b_emb + pos ------------------------
__global__ void embed_kernel(const float* __restrict__ x, const float* __restrict__ W,
                             const float* __restrict__ be, const float* __restrict__ pos){
  int row = blockIdx.x;
  int n = row & 8191;
  int d = threadIdx.x;
  __shared__ float xs[8];
  if (d < 5) xs[d] = x[row*5+d];
  __syncthreads();
  float acc = be[d] + pos[n*DIM+d];
  #pragma unroll
  for (int k=0;k<5;k++) acc = fmaf(xs[k], W[k*DIM+d], acc);
  g_h[row*DIM+d] = acc;
}

// ---------------- layernorm (writes pre-split bf16 hi/lo) ------------------
__global__ void ln_kernel(const float* __restrict__ gl, const float* __restrict__ bl){
  int row = blockIdx.x, d = threadIdx.x;
  float v = g_h[row*DIM+d];
  __shared__ float red[8];
  float s = v;
  #pragma unroll
  for (int o=16;o>0;o>>=1) s += __shfl_xor_sync(0xffffffffu, s, o);
  if ((d&31)==0) red[d>>5] = s;
  __syncthreads();
  float tot = 0.f;
  #pragma unroll
  for (int i=0;i<8;i++) tot += red[i];
  float mu = tot * (1.0f/DIM);
  float dv = v - mu;
  __syncthreads();
  float sq = dv*dv;
  #pragma unroll
  for (int o=16;o>0;o>>=1) sq += __shfl_xor_sync(0xffffffffu, sq, o);
  if ((d&31)==0) red[d>>5] = sq;
  __syncthreads();
  float vt = 0.f;
  #pragma unroll
  for (int i=0;i<8;i++) vt += red[i];
  float var = vt*(1.0f/DIM);
  float y = fmaf(dv*rsqrtf(var+1e-5f), gl[d], bl[d]);
  __nv_bfloat16 h = __float2bfloat16(y);
  g_axh[row*DIM+d] = h;
  g_axl[row*DIM+d] = __float2bfloat16(y - __bfloat162float(h));
}

// ---------------- split-bf16 tensor-core GEMM (pipelined + ldmatrix) -------
// C = A@B via Ahi*Bhi + Ahi*Blo + Alo*Bhi (fp32 accum)
// MODE 0: g_hid = silu(nx @ Wh + bh)    [32768,256]x[256,1024]
// MODE 1: g_qk  = silu(nx @ Wqk + bqk)  [32768,256]x[256,64]
// MODE 2: g_h  += quad @ Wo + bo        [32768,512]x[512,256]
// CTA 128x64, k-tile 32, 8 warps (4m x 2n), double-buffered smem +
// register prefetch, ldmatrix.x4 fragment loads. No cp.async.
#define ABUF 2560   // 128*20 u32
#define BBUF 1280   // 64*20 u32
#define GSM ((2*ABUF*2 + 2*BBUF*2)*4)  // 61440 bytes

#define BMMA(acc, a, b0, b1) \
  asm volatile("mma.sync.aligned.m16n8k16.row.col.f32.bf16.bf16.f32 " \
    "{%0,%1,%2,%3}, {%4,%5,%6,%7}, {%8,%9}, {%0,%1,%2,%3};\n" \
    : "+f"(acc[0]),"+f"(acc[1]),"+f"(acc[2]),"+f"(acc[3]) \
    : "r"(a[0]),"r"(a[1]),"r"(a[2]),"r"(a[3]), "r"(b0),"r"(b1))

#define LDSM4(d0,d1,d2,d3,a) \
  asm volatile("ldmatrix.sync.aligned.m8n8.x4.shared.b16 {%0,%1,%2,%3}, [%4];" \
    : "=r"(d0),"=r"(d1),"=r"(d2),"=r"(d3) : "r"(a))

#define LDTILE(kt) do{ \
  size_t ko = (size_t)(kt)*32 + ac; \
  pah[0] = *(const uint4*)(Ah + (size_t)(m0+ar0)*K + ko); \
  pal[0] = *(const uint4*)(Al + (size_t)(m0+ar0)*K + ko); \
  pah[1] = *(const uint4*)(Ah + (size_t)(m0+ar0+64)*K + ko); \
  pal[1] = *(const uint4*)(Al + (size_t)(m0+ar0+64)*K + ko); \
  pbh    = *(const uint4*)(Bh_ + (size_t)(n0+ar0)*K + ko); \
  pbl    = *(const uint4*)(Bl_ + (size_t)(n0+ar0)*K + ko); \
}while(0)

#define STTILE(buf) do{ \
  *(uint4*)&AH[(buf)*ABUF + ar0*20 + acu] = pah[0]; \
  *(uint4*)&AL[(buf)*ABUF + ar0*20 + acu] = pal[0]; \
  *(uint4*)&AH[(buf)*ABUF + (ar0+64)*20 + acu] = pah[1]; \
  *(uint4*)&AL[(buf)*ABUF + (ar0+64)*20 + acu] = pal[1]; \
  *(uint4*)&BH[(buf)*BBUF + ar0*20 + acu] = pbh; \
  *(uint4*)&BL[(buf)*BBUF + ar0*20 + acu] = pbl; \
}while(0)

template<int MODE>
__global__ void __launch_bounds__(256) mma_gemm(int woff, const float* __restrict__ bias){
  constexpr int N  = (MODE==0)?H2:(MODE==1)?QKD:DIM;
  constexpr int K  = (MODE==2)?HIDW:DIM;
  constexpr int KT = K/32;

  const __nv_bfloat16* Ah = (MODE==2)? g_aqh : g_axh;
  const __nv_bfloat16* Al = (MODE==2)? g_aql : g_axl;
  const __nv_bfloat16* Bh_ = g_wh + woff;
  const __nv_bfloat16* Bl_ = g_wl + woff;
  float* C = (MODE==0) ? g_hid : (MODE==1) ? g_qk : g_h;

  extern __shared__ uint32_t smu[];
  uint32_t* AH = smu;
  uint32_t* AL = smu + 2*ABUF;
  uint32_t* BH = smu + 4*ABUF;
  uint32_t* BL = smu + 4*ABUF + 2*BBUF;
  uint32_t smb = (uint32_t)__cvta_generic_to_shared(smu);

  int tid = threadIdx.x;
  int warp = tid>>5, lane = tid&31;
  int gq = lane>>2, tig = lane&3;
  int wm = (warp>>1)*32, wn = (warp&1)*32;
  int m0 = blockIdx.y*128, n0 = blockIdx.x*64;

  int ar0 = tid>>2;            // A rows ar0, ar0+64; B row ar0 (0..63)
  int ac  = (tid&3)*8;         // bf16 col within k-tile
  int acu = (tid&3)*4;         // u32 col

  // ldmatrix per-lane offsets (u32 units within one buffer)
  int lg = lane>>3, lr = lane&7;
  uint32_t aoff[2], boff[2];
  #pragma unroll
  for (int mt=0;mt<2;mt++)
    aoff[mt] = (uint32_t)((wm + mt*16 + (lg&1)*8 + lr)*20 + (lg>>1)*4);
  #pragma unroll
  for (int p=0;p<2;p++)
    boff[p] = (uint32_t)((wn + p*16 + (lg>>1)*8 + lr)*20 + (lg&1)*4);

  float acc[2][4][4];
  #pragma unroll
  for (int mt=0;mt<2;mt++)
    #pragma unroll
    for (int nt=0;nt<4;nt++)
      #pragma unroll
      for (int c=0;c<4;c++) acc[mt][nt][c]=0.f;

  uint4 pah[2], pal[2], pbh, pbl;

  LDTILE(0);
  STTILE(0);
  __syncthreads();

  for (int kt=0; kt<KT; kt++){
    int buf = kt&1;
    if (kt+1 < KT) LDTILE(kt+1);

    uint32_t abase  = smb + (buf*ABUF)*4;
    uint32_t albase = smb + ((2+buf)*ABUF)*4;
    uint32_t bbase  = smb + (4*ABUF + buf*BBUF)*4;
    uint32_t blbase = smb + (4*ABUF + (2+buf)*BBUF)*4;

    #pragma unroll
    for (int kk=0;kk<2;kk++){
      uint32_t ah[2][4], al[2][4];
      #pragma unroll
      for (int mt=0;mt<2;mt++){
        LDSM4(ah[mt][0],ah[mt][1],ah[mt][2],ah[mt][3], abase  + (aoff[mt] + kk*8)*4);
        LDSM4(al[mt][0],al[mt][1],al[mt][2],al[mt][3], albase + (aoff[mt] + kk*8)*4);
      }
      uint32_t bh[2][4], bl[2][4];
      #pragma unroll
      for (int p=0;p<2;p++){
        LDSM4(bh[p][0],bh[p][1],bh[p][2],bh[p][3], bbase  + (boff[p] + kk*8)*4);
        LDSM4(bl[p][0],bl[p][1],bl[p][2],bl[p][3], blbase + (boff[p] + kk*8)*4);
      }
      #pragma unroll
      for (int mt=0;mt<2;mt++)
        #pragma unroll
        for (int p=0;p<2;p++)
          #pragma unroll
          for (int h=0;h<2;h++){
            float* a4 = acc[mt][p*2+h];
            BMMA(a4, ah[mt], bh[p][h*2], bh[p][h*2+1]);
            BMMA(a4, ah[mt], bl[p][h*2], bl[p][h*2+1]);
            BMMA(a4, al[mt], bh[p][h*2], bh[p][h*2+1]);
          }
    }
    if (kt+1 < KT) STTILE(buf^1);
    __syncthreads();
  }

  // epilogue
  #pragma unroll
  for (int mt=0;mt<2;mt++){
    int r0 = m0 + wm + mt*16 + gq;
    #pragma unroll
    for (int nt=0;nt<4;nt++){
      int c0 = n0 + wn + nt*8 + tig*2;
      float b0 = bias[c0], b1 = bias[c0+1];
      #pragma unroll
      for (int h=0;h<2;h++){
        int row = r0 + h*8;
        float v0 = acc[mt][nt][h*2+0] + b0;
        float v1 = acc[mt][nt][h*2+1] + b1;
        float* p = C + (size_t)row*N + c0;
        if (MODE==2){ p[0] += v0; p[1] += v1; }
        else        { p[0] = siluf(v0); p[1] = siluf(v1); }
      }
    }
  }
}

// ---------------- T5 rel-pos bias table ------------------------------------
__global__ void bias_kernel(const float* __restrict__ relb){
  int i = blockIdx.x, j = threadIdx.x;
  int n = i - j; if (n < 0) n = 0;
  int bucket;
  if (n < 16) bucket = n;
  else {
    float t = logf((float)n * (1.0f/16.0f)) * (16.0f / 2.0794415416798357f); // /log(8)
    int val = 16 + (int)t;
    bucket = val < 31 ? val : 31;
  }
  g_bias[i*GRP + j] = relb[bucket]*8.0f;   // * sqrt(QKD)
}

// ---------------- fused quad attention + K^T V -----------------------------
#define SQS 68
#define SAS 260
#define ATTN_SMEM ((256*SQS + 64*SQS + 64*SAS + 64*128 + 6*64)*4)

__global__ void __launch_bounds__(256) attn_kernel(const float* __restrict__ gamma,
                                                   const float* __restrict__ beta){
  extern __shared__ float sm[];
  float* sQK  = sm;                 // [256][68]  raw silu(qk)
  float* sQQ  = sQK + 256*SQS;      // [64][68]   quad queries (this i-tile)
  float* sAtt = sQQ + 64*SQS;       // [64][260]  laplace attn tile
  float* sV   = sAtt + 64*SAS;      // [64][128]  v chunk
  float* sG   = sV + 64*128;        // g0,b0,g2,b2,g3,b3 (6*64)
  int it = blockIdx.x, g = blockIdx.y, b = blockIdx.z;
  int tid = threadIdx.x;
  size_t base = (size_t)(b*NG + g)*GRP;

  #pragma unroll
  for (int i=0;i<16;i++){
    int idx = i*256+tid;
    int r = idx>>4, c4 = (idx&15)*4;
    *(float4*)&sQK[r*SQS + c4] = *(const float4*)(g_qk + (base+r)*QKD + c4);
  }
  if (tid < 64){
    sG[tid]     = gamma[tid];      sG[64+tid]  = beta[tid];        // head 0 (qq)
    sG[128+tid] = gamma[128+tid];  sG[192+tid] = beta[128+tid];    // head 2 (qk)
    sG[256+tid] = gamma[192+tid];  sG[320+tid] = beta[192+tid];    // head 3 (lk)
  }
  __syncthreads();
  #pragma unroll
  for (int i=0;i<16;i++){
    int idx = i*256+tid; int ii = idx>>6, d = idx&63;
    sQQ[ii*SQS+d] = fmaf(sQK[(it*64+ii)*SQS + d], sG[d], sG[64+d]);
  }
  __syncthreads();

  int ty = tid>>5, tx = tid&31;
  // phase A: sim = qq.qkk/256 + bias -> laplace -> causal mask
  {
    float acc[8][8];
    #pragma unroll
    for (int r=0;r<8;r++)
      #pragma unroll
      for (int c=0;c<8;c++) acc[r][c]=0.f;
    #pragma unroll 4
    for (int d=0; d<64; d++){
      float g2 = sG[128+d], b2 = sG[192+d];
      float a[8], kk[8];
      #pragma unroll
      for (int r=0;r<8;r++) a[r] = sQQ[(ty*8+r)*SQS + d];
      #pragma unroll
      for (int c=0;c<8;c++) kk[c] = fmaf(sQK[(tx + 32*c)*SQS + d], g2, b2);
      #pragma unroll
      for (int r=0;r<8;r++)
        #pragma unroll
        for (int c=0;c<8;c++) acc[r][c] = fmaf(a[r], kk[c], acc[r][c]);
    }
    #pragma unroll
    for (int r=0;r<8;r++){
      int ig = it*64 + ty*8 + r;
      #pragma unroll
      for (int c=0;c<8;c++){
        int j = tx + 32*c;
        float s = acc[r][c]*(1.0f/256.0f) + g_bias[ig*GRP + j];
        float at = (j <= ig) ? 0.5f*(1.0f + erff((s - 0.70710678f)*0.79788456f)) : 0.0f;
        sAtt[(ty*8+r)*SAS + j] = at;
      }
    }
  }

  float g3r[8], b3r[8];
  #pragma unroll
  for (int r=0;r<8;r++){ g3r[r]=sG[256+ty*8+r]; b3r[r]=sG[320+ty*8+r]; }

  // phase B: quad = attn @ v, plus (it==0) kv = lk^T v / 256
  for (int et=0; et<4; et++){
    float qacc[8][4], kvacc[8][4];
    #pragma unroll
    for (int r=0;r<8;r++)
      #pragma unroll
      for (int c=0;c<4;c++){ qacc[r][c]=0.f; kvacc[r][c]=0.f; }
    for (int jc=0;jc<4;jc++){
      __syncthreads();
      #pragma unroll
      for (int i=0;i<8;i++){
        int idx = i*256+tid;
        int r = idx>>5, c4 = (idx&31)*4;
        *(float4*)&sV[r*128+c4] = *(const float4*)(g_hid + (base + jc*64 + r)*H2 + et*128 + c4);
      }
      __syncthreads();
      #pragma unroll 2
      for (int jj=0;jj<64;jj++){
        int j = jc*64 + jj;
        float4 v4 = *(float4*)&sV[jj*128 + tx*4];
        float a[8];
        #pragma unroll
        for (int r=0;r<8;r++) a[r] = sAtt[(ty*8+r)*SAS + j];
        #pragma unroll
        for (int r=0;r<8;r++){
          qacc[r][0]=fmaf(a[r],v4.x,qacc[r][0]);
          qacc[r][1]=fmaf(a[r],v4.y,qacc[r][1]);
          qacc[r][2]=fmaf(a[r],v4.z,qacc[r][2]);
          qacc[r][3]=fmaf(a[r],v4.w,qacc[r][3]);
        }
        if (it==0){
          #pragma unroll
          for (int r=0;r<8;r++){
            float lk = fmaf(sQK[j*SQS + ty*8 + r], g3r[r], b3r[r]);
            kvacc[r][0]=fmaf(lk,v4.x,kvacc[r][0]);
            kvacc[r][1]=fmaf(lk,v4.y,kvacc[r][1]);
            kvacc[r][2]=fmaf(lk,v4.z,kvacc[r][2]);
            kvacc[r][3]=fmaf(lk,v4.w,kvacc[r][3]);
          }
        }
      }
    }
    #pragma unroll
    for (int r=0;r<8;r++){
      size_t row = base + it*64 + ty*8 + r;
      float4 o; o.x=qacc[r][0]; o.y=qacc[r][1]; o.z=qacc[r][2]; o.w=qacc[r][3];
      *(float4*)(g_quad + row*HIDW + et*128 + tx*4) = o;
    }
    if (it==0){
      #pragma unroll
      for (int r=0;r<8;r++){
        float4 o;
        o.x=kvacc[r][0]*(1.0f/256.0f); o.y=kvacc[r][1]*(1.0f/256.0f);
        o.z=kvacc[r][2]*(1.0f/256.0f); o.w=kvacc[r][3]*(1.0f/256.0f);
        *(float4*)(g_kv + ((size_t)(b*NG+g)*QKD + ty*8 + r)*HIDW + et*128 + tx*4) = o;
      }
    }
  }
}

// ---------------- exclusive cumsum of kv over groups (in place) ------------
__global__ void cumsum_kernel(){
  int b = blockIdx.y;
  int idx = blockIdx.x*256 + threadIdx.x;   // 0..32767 = d*512+e
  float acc = 0.f;
  #pragma unroll
  for (int g=0; g<NG; g++){
    size_t p = ((size_t)(b*NG+g))*(QKD*HIDW) + idx;
    float cur = g_kv[p];
    g_kv[p] = acc;
    acc += cur;
  }
}

// ---------------- linear attention + gated combine (writes bf16 splits) ----
#define LIN_SMEM ((64*64 + 64*128 + 128)*4)
__global__ void __launch_bounds__(256) lin_kernel(const float* __restrict__ gamma,
                                                  const float* __restrict__ beta){
  extern __shared__ float sm[];
  float* sLQ  = sm;              // [64][64]
  float* sLKV = sLQ + 64*64;     // [64][128]
  float* sG1  = sLKV + 64*128;   // [64]
  float* sB1  = sG1 + 64;        // [64]
  int et = blockIdx.x & 3, it = blockIdx.x >> 2;
  int g = blockIdx.y, b = blockIdx.z;
  int tid = threadIdx.x, ty = tid>>5, tx = tid&31;
  size_t base = (size_t)(b*NG+g)*GRP;

  if (tid < 64){ sG1[tid]=gamma[64+tid]; sB1[tid]=beta[64+tid]; }   // head 1 (lq)
  #pragma unroll
  for (int i=0;i<4;i++){
    int idx = i*256+tid; int r = idx>>4, c4 = (idx&15)*4;
    *(float4*)&sLQ[r*64+c4] = *(const float4*)(g_qk + (base + it*64 + r)*QKD + c4);
  }
  #pragma unroll
  for (int i=0;i<8;i++){
    int idx=i*256+tid; int r=idx>>5, c4=(idx&31)*4;
    *(float4*)&sLKV[r*128+c4] = *(const float4*)(g_kv + ((size_t)(b*NG+g)*QKD + r)*HIDW + et*128 + c4);
  }
  __syncthreads();
  #pragma unroll
  for (int i=0;i<16;i++){
    int idx=i*256+tid; int r=idx>>6, d=idx&63;
    sLQ[r*64+d] = fmaf(sLQ[r*64+d], sG1[d], sB1[d]);
  }
  __syncthreads();

  float acc[8][4];
  #pragma unroll
  for (int r=0;r<8;r++){ acc[r][0]=0.f; acc[r][1]=0.f; acc[r][2]=0.f; acc[r][3]=0.f; }
  #pragma unroll 4
  for (int d=0; d<64; d++){
    float4 kv4 = *(float4*)&sLKV[d*128 + tx*4];
    float a[8];
    #pragma unroll
    for (int r=0;r<8;r++) a[r] = sLQ[(ty*8+r)*64 + d];
    #pragma unroll
    for (int r=0;r<8;r++){
      acc[r][0]=fmaf(a[r],kv4.x,acc[r][0]);
      acc[r][1]=fmaf(a[r],kv4.y,acc[r][1]);
      acc[r][2]=fmaf(a[r],kv4.z,acc[r][2]);
      acc[r][3]=fmaf(a[r],kv4.w,acc[r][3]);
    }
  }
  #pragma unroll
  for (int r=0;r<8;r++){
    size_t row = base + it*64 + ty*8 + r;
    int e = et*128 + tx*4;
    float4 q  = *(float4*)(g_quad + row*HIDW + e);
    float4 gt = *(float4*)(g_hid + row*H2 + HIDW + e);
    float o[4];
    o[0] = gt.x*(q.x+acc[r][0]);
    o[1] = gt.y*(q.y+acc[r][1]);
    o[2] = gt.z*(q.z+acc[r][2]);
    o[3] = gt.w*(q.w+acc[r][3]);
    size_t p = row*HIDW + e;
    #pragma unroll
    for (int c=0;c<4;c++){
      __nv_bfloat16 h = __float2bfloat16(o[c]);
      g_aqh[p+c] = h;
      g_aql[p+c] = __float2bfloat16(o[c] - __bfloat162float(h));
    }
  }
}

// ---------------- final mean pool + classifier -----------------------------
__global__ void mean1_kernel(){
  int c = blockIdx.x, b = blockIdx.y, d = threadIdx.x;
  float s = 0.f;
  size_t rb = (size_t)b*8192 + (size_t)c*256;
  for (int r=0;r<256;r++) s += g_h[(rb+r)*DIM + d];
  g_part[(b*NG+c)*DIM + d] = s;
}

__global__ void head_kernel(const float* __restrict__ Wd, const float* __restrict__ bd,
                            float* __restrict__ out){
  int b = blockIdx.x, d = threadIdx.x;
  float s = 0.f;
  for (int c=0;c<NG;c++) s += g_part[(b*NG+c)*DIM + d];
  s *= (1.0f/8192.0f);
  __shared__ float r0[256], r1[256];
  r0[d] = s*Wd[d*2+0];
  r1[d] = s*Wd[d*2+1];
  __syncthreads();
  for (int o=128;o>0;o>>=1){
    if (d<o){ r0[d]+=r0[d+o]; r1[d]+=r1[d+o]; }
    __syncthreads();
  }
  if (d==0){ out[b*2+0]=r0[0]+bd[0]; out[b*2+1]=r1[0]+bd[1]; }
}

// ---------------- host ------------------------------------------------------
extern "C" void kernel_launch(void* const* d_in, const int* in_sizes, int n_in,
                              void* d_out, int out_size){
  const float* x      = (const float*)d_in[0];
  const float* W_emb  = (const float*)d_in[1];
  const float* b_emb  = (const float*)d_in[2];
  const float* pos    = (const float*)d_in[3];
  const float* ln_g   = (const float*)d_in[4];
  const float* ln_b   = (const float*)d_in[5];
  const float* Wh     = (const float*)d_in[6];
  const float* bh     = (const float*)d_in[7];
  const float* Wqk    = (const float*)d_in[8];
  const float* bqk    = (const float*)d_in[9];
  const float* gamma  = (const float*)d_in[10];
  const float* beta   = (const float*)d_in[11];
  const float* relb   = (const float*)d_in[12];
  const float* Wo     = (const float*)d_in[13];
  const float* bo     = (const float*)d_in[14];
  const float* Wd     = (const float*)d_in[15];
  const float* bd     = (const float*)d_in[16];
  float* out = (float*)d_out;

  cudaFuncSetAttribute(attn_kernel, cudaFuncAttributeMaxDynamicSharedMemorySize, ATTN_SMEM);
  cudaFuncSetAttribute(lin_kernel,  cudaFuncAttributeMaxDynamicSharedMemorySize, LIN_SMEM);
  cudaFuncSetAttribute(mma_gemm<0>, cudaFuncAttributeMaxDynamicSharedMemorySize, GSM);
  cudaFuncSetAttribute(mma_gemm<1>, cudaFuncAttributeMaxDynamicSharedMemorySize, GSM);
  cudaFuncSetAttribute(mma_gemm<2>, cudaFuncAttributeMaxDynamicSharedMemorySize, GSM);

  // weight prep (transpose + split) for all layers
  for (int l=0;l<NLAYER;l++){
    int base = l*WLAYER;
    wprep_kernel<<<dim3(H2/32,  DIM/32),  dim3(32,8)>>>(Wh  + (size_t)l*DIM*H2,  base,                    DIM,  H2);
    wprep_kernel<<<dim3(QKD/32, DIM/32),  dim3(32,8)>>>(Wqk + (size_t)l*DIM*QKD, base + DIM*H2,           DIM,  QKD);
    wprep_kernel<<<dim3(DIM/32, HIDW/32), dim3(32,8)>>>(Wo  + (size_t)l*HIDW*DIM,base + DIM*H2 + DIM*QKD, HIDW, DIM);
  }

  embed_kernel<<<TOK,256>>>(x, W_emb, b_emb, pos);
  for (int l=0;l<NLAYER;l++){
    int base = l*WLAYER;
    ln_kernel<<<TOK,256>>>(ln_g + l*DIM, ln_b + l*DIM);
    mma_gemm<0><<<dim3(H2/64,  TOK/128), 256, GSM>>>(base,                    bh  + l*H2);
    mma_gemm<1><<<dim3(QKD/64, TOK/128), 256, GSM>>>(base + DIM*H2,           bqk + l*QKD);
    bias_kernel<<<GRP,GRP>>>(relb + l*32);
    attn_kernel<<<dim3(4,NG,NBATCH),256,ATTN_SMEM>>>(gamma + l*256, beta + l*256);
    cumsum_kernel<<<dim3(128,NBATCH),256>>>();
    lin_kernel<<<dim3(16,NG,NBATCH),256,LIN_SMEM>>>(gamma + l*256, beta + l*256);
    mma_gemm<2><<<dim3(DIM/64, TOK/128), 256, GSM>>>(base + DIM*H2 + DIM*QKD, bo  + l*DIM);
  }
  mean1_kernel<<<dim3(NG,NBATCH),256>>>();
  head_kernel<<<NBATCH,256>>>(Wd, bd, out);
}

// round 11
// speedup vs baseline: 1.3074x; 1.0108x over previous
#include <cuda_runtime.h>
#include <cuda_bf16.h>
#include <math.h>
#include <stdint.h>

#define TOK 32768      // B*N = 4*8192
#define DIM 256
#define HIDW 512
#define H2 1024
#define QKD 64
#define NCAT (H2+QKD)  // 1088 combined gemm01 output width
#define GRP 256
#define NG 32          // groups per sequence
#define NBATCH 4
#define NLAYER 8
#define WLAYER (NCAT*DIM + HIDW*DIM)   // 409600
#define WTOT (NLAYER*WLAYER)

// ---------------- scratch (device globals only; no allocation) -------------
__device__ float g_h[TOK*DIM];
__device__ float g_hid[TOK*H2];
__device__ float g_qk[TOK*QKD];
__device__ float g_quad[TOK*HIDW];
__device__ float g_kv[NBATCH*NG*QKD*HIDW];
__device__ float g_bias8[NLAYER*GRP*GRP];
__device__ float g_bcat[NLAYER*NCAT];
__device__ float g_part[NBATCH*NG*DIM];
// pre-split bf16 operands
__device__ __nv_bfloat16 g_axh[TOK*DIM],  g_axl[TOK*DIM];    // ln output
__device__ __nv_bfloat16 g_aqh[TOK*HIDW], g_aql[TOK*HIDW];   // gated quad+lin
__device__ __nv_bfloat16 g_wh[WTOT], g_wl[WTOT];             // packed weights [n][k]

__device__ __forceinline__ float siluf(float x){ return x/(1.0f+expf(-x)); }

// ---------------- weight prep: transpose + split to bf16 hi/lo -------------
// W (one layer = K*N) [K][N] row-major -> g_wh/g_wl at layer*WLAYER + dstBase + n*K + k
__global__ void wprep_kernel(const float* __restrict__ W, int K, int N, int dstBase){
  __shared__ float t[32][33];
  int l = blockIdx.z;
  const float* Ws = W + (size_t)l*K*N;
  size_t dbase = (size_t)l*WLAYER + dstBase;
  int n0 = blockIdx.x*32, k0 = blockIdx.y*32;
  int tx = threadIdx.x, ty = threadIdx.y;   // 32 x 8
  #pragma unroll
  for (int i=0;i<32;i+=8)
    t[ty+i][tx] = Ws[(size_t)(k0+ty+i)*N + n0+tx];
  __syncthreads();
  #pragma unroll
  for (int i=0;i<32;i+=8){
    float v = t[tx][ty+i];
    __nv_bfloat16 h = __float2bfloat16(v);
    float hf = __bfloat162float(h);
    size_t o = dbase + (size_t)(n0+ty+i)*K + k0+tx;
    g_wh[o] = h;
    g_wl[o] = __float2bfloat16(v - hf);
  }
}

// ---------------- misc prep: rel-pos bias tables + concat biases -----------
__global__ void misc_prep(const float* __restrict__ relb, const float* __restrict__ bh,
                          const float* __restrict__ bqk){
  int i = blockIdx.x, l = blockIdx.y, j = threadIdx.x;
  int n = i - j; if (n < 0) n = 0;
  int bucket;
  if (n < 16) bucket = n;
  else {
    float t = logf((float)n * (1.0f/16.0f)) * (16.0f / 2.0794415416798357f); // /log(8)
    int val = 16 + (int)t;
    bucket = val < 31 ? val : 31;
  }
  g_bias8[((size_t)l*GRP + i)*GRP + j] = relb[l*32 + bucket]*8.0f;   // * sqrt(QKD)
  int idx = i*GRP + j;
  if (idx < NCAT)
    g_bcat[l*NCAT + idx] = (idx < H2) ? bh[l*H2 + idx] : bqk[l*QKD + idx - H2];
}

// ---------------- fused embed + layer-0 layernorm --------------------------
__global__ void embed_ln_kernel(const float* __restrict__ x, const float* __restrict__ W,
                                const float* __restrict__ be, const float* __restrict__ pos,
                                const float* __restrict__ gl, const float* __restrict__ bl){
  int row = blockIdx.x;
  int n = row & 8191;
  int d = threadIdx.x;
  __shared__ float xs[8];
  __shared__ float red[8];
  if (d < 5) xs[d] = x[row*5+d];
  __syncthreads();
  float v = be[d] + pos[n*DIM+d];
  #pragma unroll
  for (int k=0;k<5;k++) v = fmaf(xs[k], W[k*DIM+d], v);
  g_h[row*DIM+d] = v;
  // layernorm on v
  float s = v;
  #pragma unroll
  for (int o=16;o>0;o>>=1) s += __shfl_xor_sync(0xffffffffu, s, o);
  if ((d&31)==0) red[d>>5] = s;
  __syncthreads();
  float tot = 0.f;
  #pragma unroll
  for (int i=0;i<8;i++) tot += red[i];
  float mu = tot * (1.0f/DIM);
  float dv = v - mu;
  __syncthreads();
  float sq = dv*dv;
  #pragma unroll
  for (int o=16;o>0;o>>=1) sq += __shfl_xor_sync(0xffffffffu, sq, o);
  if ((d&31)==0) red[d>>5] = sq;
  __syncthreads();
  float vt = 0.f;
  #pragma unroll
  for (int i=0;i<8;i++) vt += red[i];
  float var = vt*(1.0f/DIM);
  float y = fmaf(dv*rsqrtf(var+1e-5f), gl[d], bl[d]);
  __nv_bfloat16 h = __float2bfloat16(y);
  g_axh[row*DIM+d] = h;
  g_axl[row*DIM+d] = __float2bfloat16(y - __bfloat162float(h));
}

// ---------------- layernorm (layers 1..7) ----------------------------------
__global__ void ln_kernel(const float* __restrict__ gl, const float* __restrict__ bl){
  int row = blockIdx.x, d = threadIdx.x;
  float v = g_h[row*DIM+d];
  __shared__ float red[8];
  float s = v;
  #pragma unroll
  for (int o=16;o>0;o>>=1) s += __shfl_xor_sync(0xffffffffu, s, o);
  if ((d&31)==0) red[d>>5] = s;
  __syncthreads();
  float tot = 0.f;
  #pragma unroll
  for (int i=0;i<8;i++) tot += red[i];
  float mu = tot * (1.0f/DIM);
  float dv = v - mu;
  __syncthreads();
  float sq = dv*dv;
  #pragma unroll
  for (int o=16;o>0;o>>=1) sq += __shfl_xor_sync(0xffffffffu, sq, o);
  if ((d&31)==0) red[d>>5] = sq;
  __syncthreads();
  float vt = 0.f;
  #pragma unroll
  for (int i=0;i<8;i++) vt += red[i];
  float var = vt*(1.0f/DIM);
  float y = fmaf(dv*rsqrtf(var+1e-5f), gl[d], bl[d]);
  __nv_bfloat16 h = __float2bfloat16(y);
  g_axh[row*DIM+d] = h;
  g_axl[row*DIM+d] = __float2bfloat16(y - __bfloat162float(h));
}

// ---------------- split-bf16 tensor-core GEMM (pipelined + ldmatrix) -------
// C = A@B via Ahi*Bhi + Ahi*Blo + Alo*Bhi (fp32 accum)
// MODE 0: [hid|qk] = silu(nx @ [Wh|Wqk] + bcat)  [32768,256]x[256,1088]
// MODE 2: g_h  += quad @ Wo + bo                 [32768,512]x[512,256]
// CTA 128x64, k-tile 32, 8 warps (4m x 2n), double-buffered smem +
// register prefetch, ldmatrix.x4 fragment loads. No cp.async.
#define ABUF 2560   // 128*20 u32
#define BBUF 1280   // 64*20 u32
#define GSM ((2*ABUF*2 + 2*BBUF*2)*4)  // 61440 bytes

#define BMMA(acc, a, b0, b1) \
  asm volatile("mma.sync.aligned.m16n8k16.row.col.f32.bf16.bf16.f32 " \
    "{%0,%1,%2,%3}, {%4,%5,%6,%7}, {%8,%9}, {%0,%1,%2,%3};\n" \
    : "+f"(acc[0]),"+f"(acc[1]),"+f"(acc[2]),"+f"(acc[3]) \
    : "r"(a[0]),"r"(a[1]),"r"(a[2]),"r"(a[3]), "r"(b0),"r"(b1))

#define LDSM4(d0,d1,d2,d3,a) \
  asm volatile("ldmatrix.sync.aligned.m8n8.x4.shared.b16 {%0,%1,%2,%3}, [%4];" \
    : "=r"(d0),"=r"(d1),"=r"(d2),"=r"(d3) : "r"(a))

#define LDTILE(kt) do{ \
  size_t ko = (size_t)(kt)*32 + ac; \
  pah[0] = *(const uint4*)(Ah + (size_t)(m0+ar0)*K + ko); \
  pal[0] = *(const uint4*)(Al + (size_t)(m0+ar0)*K + ko); \
  pah[1] = *(const uint4*)(Ah + (size_t)(m0+ar0+64)*K + ko); \
  pal[1] = *(const uint4*)(Al + (size_t)(m0+ar0+64)*K + ko); \
  pbh    = *(const uint4*)(Bh_ + (size_t)(n0+ar0)*K + ko); \
  pbl    = *(const uint4*)(Bl_ + (size_t)(n0+ar0)*K + ko); \
}while(0)

#define STTILE(buf) do{ \
  *(uint4*)&AH[(buf)*ABUF + ar0*20 + acu] = pah[0]; \
  *(uint4*)&AL[(buf)*ABUF + ar0*20 + acu] = pal[0]; \
  *(uint4*)&AH[(buf)*ABUF + (ar0+64)*20 + acu] = pah[1]; \
  *(uint4*)&AL[(buf)*ABUF + (ar0+64)*20 + acu] = pal[1]; \
  *(uint4*)&BH[(buf)*BBUF + ar0*20 + acu] = pbh; \
  *(uint4*)&BL[(buf)*BBUF + ar0*20 + acu] = pbl; \
}while(0)

template<int MODE>
__global__ void __launch_bounds__(256) mma_gemm(int woff, const float* __restrict__ bias_p,
                                                int lay){
  constexpr int K  = (MODE==2)?HIDW:DIM;
  constexpr int KT = K/32;

  const __nv_bfloat16* Ah = (MODE==2)? g_aqh : g_axh;
  const __nv_bfloat16* Al = (MODE==2)? g_aql : g_axl;
  const __nv_bfloat16* Bh_ = g_wh + woff;
  const __nv_bfloat16* Bl_ = g_wl + woff;
  const float* bias = (MODE==0) ? (g_bcat + lay*NCAT) : bias_p;

  extern __shared__ uint32_t smu[];
  uint32_t* AH = smu;
  uint32_t* AL = smu + 2*ABUF;
  uint32_t* BH = smu + 4*ABUF;
  uint32_t* BL = smu + 4*ABUF + 2*BBUF;
  uint32_t smb = (uint32_t)__cvta_generic_to_shared(smu);

  int tid = threadIdx.x;
  int warp = tid>>5, lane = tid&31;
  int gq = lane>>2, tig = lane&3;
  int wm = (warp>>1)*32, wn = (warp&1)*32;
  int m0 = blockIdx.y*128, n0 = blockIdx.x*64;

  int ar0 = tid>>2;            // A rows ar0, ar0+64; B row ar0 (0..63)
  int ac  = (tid&3)*8;         // bf16 col within k-tile
  int acu = (tid&3)*4;         // u32 col

  // ldmatrix per-lane offsets (u32 units within one buffer)
  int lg = lane>>3, lr = lane&7;
  uint32_t aoff[2], boff[2];
  #pragma unroll
  for (int mt=0;mt<2;mt++)
    aoff[mt] = (uint32_t)((wm + mt*16 + (lg&1)*8 + lr)*20 + (lg>>1)*4);
  #pragma unroll
  for (int p=0;p<2;p++)
    boff[p] = (uint32_t)((wn + p*16 + (lg>>1)*8 + lr)*20 + (lg&1)*4);

  float acc[2][4][4];
  #pragma unroll
  for (int mt=0;mt<2;mt++)
    #pragma unroll
    for (int nt=0;nt<4;nt++)
      #pragma unroll
      for (int c=0;c<4;c++) acc[mt][nt][c]=0.f;

  uint4 pah[2], pal[2], pbh, pbl;

  LDTILE(0);
  STTILE(0);
  __syncthreads();

  for (int kt=0; kt<KT; kt++){
    int buf = kt&1;
    if (kt+1 < KT) LDTILE(kt+1);

    uint32_t abase  = smb + (buf*ABUF)*4;
    uint32_t albase = smb + ((2+buf)*ABUF)*4;
    uint32_t bbase  = smb + (4*ABUF + buf*BBUF)*4;
    uint32_t blbase = smb + (4*ABUF + (2+buf)*BBUF)*4;

    #pragma unroll
    for (int kk=0;kk<2;kk++){
      uint32_t ah[2][4], al[2][4];
      #pragma unroll
      for (int mt=0;mt<2;mt++){
        LDSM4(ah[mt][0],ah[mt][1],ah[mt][2],ah[mt][3], abase  + (aoff[mt] + kk*8)*4);
        LDSM4(al[mt][0],al[mt][1],al[mt][2],al[mt][3], albase + (aoff[mt] + kk*8)*4);
      }
      uint32_t bh[2][4], bl[2][4];
      #pragma unroll
      for (int p=0;p<2;p++){
        LDSM4(bh[p][0],bh[p][1],bh[p][2],bh[p][3], bbase  + (boff[p] + kk*8)*4);
        LDSM4(bl[p][0],bl[p][1],bl[p][2],bl[p][3], blbase + (boff[p] + kk*8)*4);
      }
      #pragma unroll
      for (int mt=0;mt<2;mt++)
        #pragma unroll
        for (int p=0;p<2;p++)
          #pragma unroll
          for (int h=0;h<2;h++){
            float* a4 = acc[mt][p*2+h];
            BMMA(a4, ah[mt], bh[p][h*2], bh[p][h*2+1]);
            BMMA(a4, ah[mt], bl[p][h*2], bl[p][h*2+1]);
            BMMA(a4, al[mt], bh[p][h*2], bh[p][h*2+1]);
          }
    }
    if (kt+1 < KT) STTILE(buf^1);
    __syncthreads();
  }

  // epilogue
  bool isqk = (MODE==0) && (n0 >= H2);
  #pragma unroll
  for (int mt=0;mt<2;mt++){
    int r0 = m0 + wm + mt*16 + gq;
    #pragma unroll
    for (int nt=0;nt<4;nt++){
      int c0 = n0 + wn + nt*8 + tig*2;
      float b0 = bias[c0], b1 = bias[c0+1];
      #pragma unroll
      for (int h=0;h<2;h++){
        int row = r0 + h*8;
        float v0 = acc[mt][nt][h*2+0] + b0;
        float v1 = acc[mt][nt][h*2+1] + b1;
        if (MODE==2){
          float* p = g_h + (size_t)row*DIM + c0;
          p[0] += v0; p[1] += v1;
        } else if (isqk){
          float* p = g_qk + (size_t)row*QKD + (c0 - H2);
          p[0] = siluf(v0); p[1] = siluf(v1);
        } else {
          float* p = g_hid + (size_t)row*H2 + c0;
          p[0] = siluf(v0); p[1] = siluf(v1);
        }
      }
    }
  }
}

// ---------------- fused quad attention + K^T V -----------------------------
#define SQS 68
#define SAS 260
#define ATTN_SMEM ((256*SQS + 64*SQS + 64*SAS + 64*128 + 6*64)*4)

__global__ void __launch_bounds__(256) attn_kernel(const float* __restrict__ gamma,
                                                   const float* __restrict__ beta,
                                                   int lay){
  extern __shared__ float sm[];
  float* sQK  = sm;                 // [256][68]  raw silu(qk)
  float* sQQ  = sQK + 256*SQS;      // [64][68]   quad queries (this i-tile)
  float* sAtt = sQQ + 64*SQS;       // [64][260]  laplace attn tile
  float* sV   = sAtt + 64*SAS;      // [64][128]  v chunk
  float* sG   = sV + 64*128;        // g0,b0,g2,b2,g3,b3 (6*64)
  int it = blockIdx.x, g = blockIdx.y, b = blockIdx.z;
  int tid = threadIdx.x;
  size_t base = (size_t)(b*NG + g)*GRP;
  const float* btab = g_bias8 + (size_t)lay*GRP*GRP;

  #pragma unroll
  for (int i=0;i<16;i++){
    int idx = i*256+tid;
    int r = idx>>4, c4 = (idx&15)*4;
    *(float4*)&sQK[r*SQS + c4] = *(const float4*)(g_qk + (base+r)*QKD + c4);
  }
  if (tid < 64){
    sG[tid]     = gamma[tid];      sG[64+tid]  = beta[tid];        // head 0 (qq)
    sG[128+tid] = gamma[128+tid];  sG[192+tid] = beta[128+tid];    // head 2 (qk)
    sG[256+tid] = gamma[192+tid];  sG[320+tid] = beta[192+tid];    // head 3 (lk)
  }
  __syncthreads();
  #pragma unroll
  for (int i=0;i<16;i++){
    int idx = i*256+tid; int ii = idx>>6, d = idx&63;
    sQQ[ii*SQS+d] = fmaf(sQK[(it*64+ii)*SQS + d], sG[d], sG[64+d]);
  }
  __syncthreads();

  int ty = tid>>5, tx = tid&31;
  // phase A: sim = qq.qkk/256 + bias -> laplace -> causal mask
  {
    float acc[8][8];
    #pragma unroll
    for (int r=0;r<8;r++)
      #pragma unroll
      for (int c=0;c<8;c++) acc[r][c]=0.f;
    #pragma unroll 4
    for (int d=0; d<64; d++){
      float g2 = sG[128+d], b2 = sG[192+d];
      float a[8], kk[8];
      #pragma unroll
      for (int r=0;r<8;r++) a[r] = sQQ[(ty*8+r)*SQS + d];
      #pragma unroll
      for (int c=0;c<8;c++) kk[c] = fmaf(sQK[(tx + 32*c)*SQS + d], g2, b2);
      #pragma unroll
      for (int r=0;r<8;r++)
        #pragma unroll
        for (int c=0;c<8;c++) acc[r][c] = fmaf(a[r], kk[c], acc[r][c]);
    }
    #pragma unroll
    for (int r=0;r<8;r++){
      int ig = it*64 + ty*8 + r;
      #pragma unroll
      for (int c=0;c<8;c++){
        int j = tx + 32*c;
        float s = acc[r][c]*(1.0f/256.0f) + btab[ig*GRP + j];
        float at = (j <= ig) ? 0.5f*(1.0f + erff((s - 0.70710678f)*0.79788456f)) : 0.0f;
        sAtt[(ty*8+r)*SAS + j] = at;
      }
    }
  }

  float g3r[8], b3r[8];
  #pragma unroll
  for (int r=0;r<8;r++){ g3r[r]=sG[256+ty*8+r]; b3r[r]=sG[320+ty*8+r]; }

  // phase B: quad = attn @ v, plus (it==0) kv = lk^T v / 256
  for (int et=0; et<4; et++){
    float qacc[8][4], kvacc[8][4];
    #pragma unroll
    for (int r=0;r<8;r++)
      #pragma unroll
      for (int c=0;c<4;c++){ qacc[r][c]=0.f; kvacc[r][c]=0.f; }
    for (int jc=0;jc<4;jc++){
      __syncthreads();
      #pragma unroll
      for (int i=0;i<8;i++){
        int idx = i*256+tid;
        int r = idx>>5, c4 = (idx&31)*4;
        *(float4*)&sV[r*128+c4] = *(const float4*)(g_hid + (base + jc*64 + r)*H2 + et*128 + c4);
      }
      __syncthreads();
      #pragma unroll 2
      for (int jj=0;jj<64;jj++){
        int j = jc*64 + jj;
        float4 v4 = *(float4*)&sV[jj*128 + tx*4];
        float a[8];
        #pragma unroll
        for (int r=0;r<8;r++) a[r] = sAtt[(ty*8+r)*SAS + j];
        #pragma unroll
        for (int r=0;r<8;r++){
          qacc[r][0]=fmaf(a[r],v4.x,qacc[r][0]);
          qacc[r][1]=fmaf(a[r],v4.y,qacc[r][1]);
          qacc[r][2]=fmaf(a[r],v4.z,qacc[r][2]);
          qacc[r][3]=fmaf(a[r],v4.w,qacc[r][3]);
        }
        if (it==0){
          #pragma unroll
          for (int r=0;r<8;r++){
            float lk = fmaf(sQK[j*SQS + ty*8 + r], g3r[r], b3r[r]);
            kvacc[r][0]=fmaf(lk,v4.x,kvacc[r][0]);
            kvacc[r][1]=fmaf(lk,v4.y,kvacc[r][1]);
            kvacc[r][2]=fmaf(lk,v4.z,kvacc[r][2]);
            kvacc[r][3]=fmaf(lk,v4.w,kvacc[r][3]);
          }
        }
      }
    }
    #pragma unroll
    for (int r=0;r<8;r++){
      size_t row = base + it*64 + ty*8 + r;
      float4 o; o.x=qacc[r][0]; o.y=qacc[r][1]; o.z=qacc[r][2]; o.w=qacc[r][3];
      *(float4*)(g_quad + row*HIDW + et*128 + tx*4) = o;
    }
    if (it==0){
      #pragma unroll
      for (int r=0;r<8;r++){
        float4 o;
        o.x=kvacc[r][0]*(1.0f/256.0f); o.y=kvacc[r][1]*(1.0f/256.0f);
        o.z=kvacc[r][2]*(1.0f/256.0f); o.w=kvacc[r][3]*(1.0f/256.0f);
        *(float4*)(g_kv + ((size_t)(b*NG+g)*QKD + ty*8 + r)*HIDW + et*128 + tx*4) = o;
      }
    }
  }
}

// ---------------- exclusive cumsum of kv over groups (in place) ------------
__global__ void cumsum_kernel(){
  int b = blockIdx.y;
  int idx = blockIdx.x*256 + threadIdx.x;   // 0..32767 = d*512+e
  float acc = 0.f;
  #pragma unroll
  for (int g=0; g<NG; g++){
    size_t p = ((size_t)(b*NG+g))*(QKD*HIDW) + idx;
    float cur = g_kv[p];
    g_kv[p] = acc;
    acc += cur;
  }
}

// ---------------- linear attention + gated combine (writes bf16 splits) ----
#define LIN_SMEM ((64*64 + 64*128 + 128)*4)
__global__ void __launch_bounds__(256) lin_kernel(const float* __restrict__ gamma,
                                                  const float* __restrict__ beta){
  extern __shared__ float sm[];
  float* sLQ  = sm;              // [64][64]
  float* sLKV = sLQ + 64*64;     // [64][128]
  float* sG1  = sLKV + 64*128;   // [64]
  float* sB1  = sG1 + 64;        // [64]
  int et = blockIdx.x & 3, it = blockIdx.x >> 2;
  int g = blockIdx.y, b = blockIdx.z;
  int tid = threadIdx.x, ty = tid>>5, tx = tid&31;
  size_t base = (size_t)(b*NG+g)*GRP;

  if (tid < 64){ sG1[tid]=gamma[64+tid]; sB1[tid]=beta[64+tid]; }   // head 1 (lq)
  #pragma unroll
  for (int i=0;i<4;i++){
    int idx = i*256+tid; int r = idx>>4, c4 = (idx&15)*4;
    *(float4*)&sLQ[r*64+c4] = *(const float4*)(g_qk + (base + it*64 + r)*QKD + c4);
  }
  #pragma unroll
  for (int i=0;i<8;i++){
    int idx=i*256+tid; int r=idx>>5, c4=(idx&31)*4;
    *(float4*)&sLKV[r*128+c4] = *(const float4*)(g_kv + ((size_t)(b*NG+g)*QKD + r)*HIDW + et*128 + c4);
  }
  __syncthreads();
  #pragma unroll
  for (int i=0;i<16;i++){
    int idx=i*256+tid; int r=idx>>6, d=idx&63;
    sLQ[r*64+d] = fmaf(sLQ[r*64+d], sG1[d], sB1[d]);
  }
  __syncthreads();

  float acc[8][4];
  #pragma unroll
  for (int r=0;r<8;r++){ acc[r][0]=0.f; acc[r][1]=0.f; acc[r][2]=0.f; acc[r][3]=0.f; }
  #pragma unroll 4
  for (int d=0; d<64; d++){
    float4 kv4 = *(float4*)&sLKV[d*128 + tx*4];
    float a[8];
    #pragma unroll
    for (int r=0;r<8;r++) a[r] = sLQ[(ty*8+r)*64 + d];
    #pragma unroll
    for (int r=0;r<8;r++){
      acc[r][0]=fmaf(a[r],kv4.x,acc[r][0]);
      acc[r][1]=fmaf(a[r],kv4.y,acc[r][1]);
      acc[r][2]=fmaf(a[r],kv4.z,acc[r][2]);
      acc[r][3]=fmaf(a[r],kv4.w,acc[r][3]);
    }
  }
  #pragma unroll
  for (int r=0;r<8;r++){
    size_t row = base + it*64 + ty*8 + r;
    int e = et*128 + tx*4;
    float4 q  = *(float4*)(g_quad + row*HIDW + e);
    float4 gt = *(float4*)(g_hid + row*H2 + HIDW + e);
    float o[4];
    o[0] = gt.x*(q.x+acc[r][0]);
    o[1] = gt.y*(q.y+acc[r][1]);
    o[2] = gt.z*(q.z+acc[r][2]);
    o[3] = gt.w*(q.w+acc[r][3]);
    size_t p = row*HIDW + e;
    #pragma unroll
    for (int c=0;c<4;c++){
      __nv_bfloat16 h = __float2bfloat16(o[c]);
      g_aqh[p+c] = h;
      g_aql[p+c] = __float2bfloat16(o[c] - __bfloat162float(h));
    }
  }
}

// ---------------- final mean pool + classifier -----------------------------
__global__ void mean1_kernel(){
  int c = blockIdx.x, b = blockIdx.y, d = threadIdx.x;
  float s = 0.f;
  size_t rb = (size_t)b*8192 + (size_t)c*256;
  for (int r=0;r<256;r++) s += g_h[(rb+r)*DIM + d];
  g_part[(b*NG+c)*DIM + d] = s;
}

__global__ void head_kernel(const float* __restrict__ Wd, const float* __restrict__ bd,
                            float* __restrict__ out){
  int b = blockIdx.x, d = threadIdx.x;
  float s = 0.f;
  for (int c=0;c<NG;c++) s += g_part[(b*NG+c)*DIM + d];
  s *= (1.0f/8192.0f);
  __shared__ float r0[256], r1[256];
  r0[d] = s*Wd[d*2+0];
  r1[d] = s*Wd[d*2+1];
  __syncthreads();
  for (int o=128;o>0;o>>=1){
    if (d<o){ r0[d]+=r0[d+o]; r1[d]+=r1[d+o]; }
    __syncthreads();
  }
  if (d==0){ out[b*2+0]=r0[0]+bd[0]; out[b*2+1]=r1[0]+bd[1]; }
}

// ---------------- host ------------------------------------------------------
extern "C" void kernel_launch(void* const* d_in, const int* in_sizes, int n_in,
                              void* d_out, int out_size){
  const float* x      = (const float*)d_in[0];
  const float* W_emb  = (const float*)d_in[1];
  const float* b_emb  = (const float*)d_in[2];
  const float* pos    = (const float*)d_in[3];
  const float* ln_g   = (const float*)d_in[4];
  const float* ln_b   = (const float*)d_in[5];
  const float* Wh     = (const float*)d_in[6];
  const float* bh     = (const float*)d_in[7];
  const float* Wqk    = (const float*)d_in[8];
  const float* bqk    = (const float*)d_in[9];
  const float* gamma  = (const float*)d_in[10];
  const float* beta   = (const float*)d_in[11];
  const float* relb   = (const float*)d_in[12];
  const float* Wo     = (const float*)d_in[13];
  const float* bo     = (const float*)d_in[14];
  const float* Wd     = (const float*)d_in[15];
  const float* bd     = (const float*)d_in[16];
  float* out = (float*)d_out;

  cudaFuncSetAttribute(attn_kernel, cudaFuncAttributeMaxDynamicSharedMemorySize, ATTN_SMEM);
  cudaFuncSetAttribute(lin_kernel,  cudaFuncAttributeMaxDynamicSharedMemorySize, LIN_SMEM);
  cudaFuncSetAttribute(mma_gemm<0>, cudaFuncAttributeMaxDynamicSharedMemorySize, GSM);
  cudaFuncSetAttribute(mma_gemm<2>, cudaFuncAttributeMaxDynamicSharedMemorySize, GSM);

  // prologue: exactly 5 launches so ncu (-s 5 -c 1) captures mma_gemm<0>
  wprep_kernel<<<dim3(H2/32,  DIM/32,  NLAYER), dim3(32,8)>>>(Wh,  DIM,  H2,  0);
  wprep_kernel<<<dim3(QKD/32, DIM/32,  NLAYER), dim3(32,8)>>>(Wqk, DIM,  QKD, H2*DIM);
  wprep_kernel<<<dim3(DIM/32, HIDW/32, NLAYER), dim3(32,8)>>>(Wo,  HIDW, DIM, NCAT*DIM);
  misc_prep<<<dim3(GRP, NLAYER), GRP>>>(relb, bh, bqk);
  embed_ln_kernel<<<TOK,256>>>(x, W_emb, b_emb, pos, ln_g, ln_b);

  for (int l=0;l<NLAYER;l++){
    int base = l*WLAYER;
    if (l > 0) ln_kernel<<<TOK,256>>>(ln_g + l*DIM, ln_b + l*DIM);
    mma_gemm<0><<<dim3(NCAT/64, TOK/128), 256, GSM>>>(base, nullptr, l);
    attn_kernel<<<dim3(4,NG,NBATCH),256,ATTN_SMEM>>>(gamma + l*256, beta + l*256, l);
    cumsum_kernel<<<dim3(128,NBATCH),256>>>();
    lin_kernel<<<dim3(16,NG,NBATCH),256,LIN_SMEM>>>(gamma + l*256, beta + l*256);
    mma_gemm<2><<<dim3(DIM/64, TOK/128), 256, GSM>>>(base + NCAT*DIM, bo + l*DIM, l);
  }
  mean1_kernel<<<dim3(NG,NBATCH),256>>>();
  head_kernel<<<NBATCH,256>>>(Wd, bd, out);
}